// round 7
// baseline (speedup 1.0000x reference)
#include <cuda_runtime.h>
#include <cstdint>
#include <cstddef>

// Problem constants (B=8, S=24, N=4096, K=9, C1=32, C2=16)
#define BS_TOT 192
#define SDIM   24
#define NPTS   4096
#define KNB    9
#define C1V    32
#define C2V    16
#define JTOT   36864   // KNB * NPTS
#define BN_EPS 1e-5f

// ---------------- device scratch (static globals: allocation-free) ----------
__device__ __align__(16) unsigned short d_P[JTOT];  // gather byte-offsets (*16)
__device__ float g_sum[SDIM * C2V];
__device__ float g_sumsq[SDIM * C2V];
// h in 4-channel-interleaved layout: g_h4[(bs*8 + qb)*NPTS + p]
__device__ float4 g_h4[(size_t)BS_TOT * 8 * NPTS];    // 96 MB
__device__ float  g_y2[(size_t)BS_TOT * C2V * NPTS];  // stage-2 out (48 MB)

// ---------------- packed f32x2 helpers (sm_103a FFMA2 path) ----------------
__device__ __forceinline__ unsigned long long pack2(float x, float y) {
    unsigned long long r;
    asm("mov.b64 %0, {%1, %2};" : "=l"(r)
        : "r"(__float_as_uint(x)), "r"(__float_as_uint(y)));
    return r;
}
__device__ __forceinline__ float2 unpack2(unsigned long long v) {
    unsigned int a, b;
    asm("mov.b64 {%0, %1}, %2;" : "=r"(a), "=r"(b) : "l"(v));
    return make_float2(__uint_as_float(a), __uint_as_float(b));
}
#define FMA2(acc, a, b) \
    asm("fma.rn.f32x2 %0, %1, %2, %0;" : "+l"(acc) : "l"(a), "l"(b))
#define ADD2(acc, a) \
    asm("add.rn.f32x2 %0, %0, %1;" : "+l"(acc) : "l"(a))

// ---------------- K1: stage 1 conv (+ folded P-build and BN zeroing) --------
__global__ void __launch_bounds__(256) k1_stage1(
    const float* __restrict__ in, const float* __restrict__ W1,
    const float* __restrict__ b1, const int* __restrict__ neigh)
{
    __shared__ __align__(16) unsigned long long sw[KNB * 16];
    __shared__ unsigned long long sb[16];
    int t = threadIdx.x;

    // folded k0: blocks 0..143 build d_P; block 0 zeroes BN accumulators
    int j = blockIdx.x * 256 + t;
    if (j < JTOT) {
        int n = j & (NPTS - 1);
        int k = j >> 12;
        d_P[j] = (unsigned short)(neigh[n * KNB + k] * 16);
    }
    if (j < SDIM * C2V) { g_sum[j] = 0.f; g_sumsq[j] = 0.f; }

    if (t < KNB * 16) {
        int q = t >> 4, oh = t & 15;
        sw[t] = pack2(W1[(2 * oh) * KNB + q], W1[(2 * oh + 1) * KNB + q]);
    }
    if (t < 16) sb[t] = pack2(b1[2 * t], b1[2 * t + 1]);
    __syncthreads();

    int g  = blockIdx.x * 256 + t;
    int bs = g >> 12;
    int pp = g & (NPTS - 1);
    const float* ip = in + (size_t)bs * JTOT;

    unsigned long long acc[16];
#pragma unroll
    for (int oh = 0; oh < 16; oh++) acc[oh] = sb[oh];

    int base = pp * KNB;
#pragma unroll
    for (int q = 0; q < KNB; q++) {
        int jt = base + q;
        float v = __ldg(ip + ((jt & (NPTS - 1)) * KNB) + (jt >> 12));
        unsigned long long v2 = pack2(v, v);
        const ulonglong2* w = (const ulonglong2*)(sw + q * 16);
#pragma unroll
        for (int oh2 = 0; oh2 < 8; oh2++) {
            ulonglong2 ww = w[oh2];
            FMA2(acc[2 * oh2],     v2, ww.x);
            FMA2(acc[2 * oh2 + 1], v2, ww.y);
        }
    }

    float4* hp = g_h4 + (size_t)bs * (8 * NPTS) + pp;
#pragma unroll
    for (int qb = 0; qb < 8; qb++) {
        float2 a = unpack2(acc[2 * qb]);
        float2 b = unpack2(acc[2 * qb + 1]);
        hp[qb * NPTS] = make_float4(fmaxf(a.x, 0.f), fmaxf(a.y, 0.f),
                                    fmaxf(b.x, 0.f), fmaxf(b.y, 0.f));
    }
}

// ---------------- K2: gather+GEMM, 8 streams, TAP-SPLIT across warp halves --
// Block (bs, qb4): channels 8qb4..8qb4+7 in two float4 smem slices.
// 256 threads: half w2 = t>>7 handles taps [w2*144, w2*144+144); tt = t&127
// is the gather row. Both halves share smem; partial accs merged via smem.
__global__ void __launch_bounds__(256, 1) k2_stage2(
    const float* __restrict__ W2, const float* __restrict__ b2)
{
    extern __shared__ char smem[];
    float4* sh_hA = (float4*)smem;                                     // 64 KB
    float4* sh_hB = (float4*)(smem + 65536);                           // 64 KB
    unsigned long long* sh_ws = (unsigned long long*)(smem + 131072);  // 36 KB
    float* red_s = (float*)(smem + 131072 + 36864);
    float* red_q = red_s + 64;

    int blk = blockIdx.x;
    int bs  = blk >> 2;
    int qb4 = blk & 3;
    int t   = threadIdx.x;
    int w2  = t >> 7;          // tap-half
    int tt  = t & 127;         // gather row

    const float4* hsrcA = g_h4 + ((size_t)bs * 8 + 2 * qb4) * NPTS;
    const float4* hsrcB = g_h4 + ((size_t)bs * 8 + 2 * qb4 + 1) * NPTS;
    for (int i = t; i < NPTS; i += 256) { sh_hA[i] = hsrcA[i]; sh_hB[i] = hsrcB[i]; }
    // splat table: sh_ws[q*16 + o] = (W2[o][q], W2[o][q])
    for (int i = t; i < 288 * 16; i += 256) {
        int q = i >> 4, o = i & 15;
        float w = W2[o * 288 + q];
        sh_ws[i] = pack2(w, w);
    }
    __syncthreads();

    unsigned long long a0[16], a1[16], a2[16], a3[16];
#pragma unroll
    for (int o = 0; o < 16; o++) {
        unsigned long long bp = (w2 == 0) ? pack2(__ldg(b2 + o), __ldg(b2 + o))
                                          : pack2(0.f, 0.f);
        a0[o] = bp; a1[o] = bp; a2[o] = bp; a3[o] = bp;
    }

    const char* hbA = (const char*)sh_hA;
    const char* hbB = (const char*)sh_hB;
    const uint4* Pp = (const uint4*)(d_P) + tt * 36 + w2 * 18;  // 18 groups/half
#pragma unroll 2
    for (int q8 = 0; q8 < 18; q8++) {
        uint4 pv = Pp[q8];
        unsigned off[8] = { pv.x & 0xFFFFu, pv.x >> 16,
                            pv.y & 0xFFFFu, pv.y >> 16,
                            pv.z & 0xFFFFu, pv.z >> 16,
                            pv.w & 0xFFFFu, pv.w >> 16 };
        const ulonglong2* wst = (const ulonglong2*)(sh_ws + (w2 * 18 + q8) * 128);
#pragma unroll
        for (int jj = 0; jj < 8; jj++) {
            ulonglong2 hA = *(const ulonglong2*)(hbA + off[jj]);
            ulonglong2 hB = *(const ulonglong2*)(hbB + off[jj]);
            const ulonglong2* ws = wst + jj * 8;
#pragma unroll
            for (int o2 = 0; o2 < 8; o2++) {
                ulonglong2 wv = ws[o2];
                FMA2(a0[2 * o2],     hA.x, wv.x);
                FMA2(a0[2 * o2 + 1], hA.x, wv.y);
                FMA2(a1[2 * o2],     hA.y, wv.x);
                FMA2(a1[2 * o2 + 1], hA.y, wv.y);
                FMA2(a2[2 * o2],     hB.x, wv.x);
                FMA2(a2[2 * o2 + 1], hB.x, wv.y);
                FMA2(a3[2 * o2],     hB.y, wv.x);
                FMA2(a3[2 * o2 + 1], hB.y, wv.y);
            }
        }
    }
    __syncthreads();   // h slices dead; reuse sh_hA as reduction buffer

    unsigned long long* red = (unsigned long long*)sh_hA;  // 128 thr * 64 ull
    if (w2 == 1) {
        unsigned long long* r = red + tt * 64;
#pragma unroll
        for (int o = 0; o < 16; o++) {
            r[o] = a0[o]; r[16 + o] = a1[o]; r[32 + o] = a2[o]; r[48 + o] = a3[o];
        }
    }
    __syncthreads();

    if (w2 == 0) {
        const unsigned long long* r = red + tt * 64;
#pragma unroll
        for (int o = 0; o < 16; o++) {
            ADD2(a0[o], r[o]);
            ADD2(a1[o], r[16 + o]);
            ADD2(a2[o], r[32 + o]);
            ADD2(a3[o], r[48 + o]);
        }

        float* dst = g_y2 + (size_t)bs * (C2V * NPTS) + qb4 * 1024 + tt;
        float vsum[16], vsq[16];
#pragma unroll
        for (int o = 0; o < 16; o++) {
            float2 f0 = unpack2(a0[o]);
            float2 f1 = unpack2(a1[o]);
            float2 f2 = unpack2(a2[o]);
            float2 f3 = unpack2(a3[o]);
            dst[o * NPTS + 0 * 128] = f0.x;
            dst[o * NPTS + 1 * 128] = f0.y;
            dst[o * NPTS + 2 * 128] = f1.x;
            dst[o * NPTS + 3 * 128] = f1.y;
            dst[o * NPTS + 4 * 128] = f2.x;
            dst[o * NPTS + 5 * 128] = f2.y;
            dst[o * NPTS + 6 * 128] = f3.x;
            dst[o * NPTS + 7 * 128] = f3.y;
            vsum[o] = (f0.x + f0.y) + (f1.x + f1.y) + (f2.x + f2.y) + (f3.x + f3.y);
            vsq[o]  = (f0.x * f0.x + f0.y * f0.y) + (f1.x * f1.x + f1.y * f1.y)
                    + (f2.x * f2.x + f2.y * f2.y) + (f3.x * f3.x + f3.y * f3.y);
        }

        int warp = tt >> 5, lane = tt & 31;
#pragma unroll
        for (int o = 0; o < 16; o++) {
            float v = vsum[o], sq = vsq[o];
#pragma unroll
            for (int off2 = 16; off2; off2 >>= 1) {
                v  += __shfl_down_sync(0xFFFFFFFFu, v,  off2);
                sq += __shfl_down_sync(0xFFFFFFFFu, sq, off2);
            }
            if (lane == 0) { red_s[warp * 16 + o] = v; red_q[warp * 16 + o] = sq; }
        }
    }
    __syncthreads();
    if (t < 16) {
        float a = red_s[t] + red_s[16 + t] + red_s[32 + t] + red_s[48 + t];
        float q = red_q[t] + red_q[16 + t] + red_q[32 + t] + red_q[48 + t];
        int s = bs % SDIM;
        atomicAdd(&g_sum[s * C2V + t], a);
        atomicAdd(&g_sumsq[s * C2V + t], q);
    }
}

// ---------------- K3: BN(inline)+relu, 4-stream gather, 144-dot, relu -------
__global__ void __launch_bounds__(256) k3_stage3(
    const float* __restrict__ W3, const float* __restrict__ b3,
    const float* __restrict__ gamma, const float* __restrict__ beta,
    float* __restrict__ out)
{
    extern __shared__ char smem3[];
    float4* sh_v = (float4*)smem3;                                   // 64 KB
    unsigned long long* sw3p = (unsigned long long*)(smem3 + 65536); // 144*8

    int blk = blockIdx.x;
    int bs  = blk >> 2;
    int cb4 = blk & 3;
    int o0  = 4 * cb4;
    int t   = threadIdx.x;
    int s   = bs % SDIM;

    // inline BN finalize for this block's 4 channels
    const float inv_cnt = 1.0f / (8.0f * (float)NPTS);
    float Ax[4], Bx[4];
#pragma unroll
    for (int c = 0; c < 4; c++) {
        int o = o0 + c;
        float mean = g_sum[s * C2V + o] * inv_cnt;
        float var  = g_sumsq[s * C2V + o] * inv_cnt - mean * mean;
        float A = __ldg(gamma + o) * rsqrtf(var + BN_EPS);
        Ax[c] = A;
        Bx[c] = __ldg(beta + o) - mean * A;
    }

    const float4* s0 = (const float4*)(g_y2 + ((size_t)bs * C2V + o0) * NPTS);
    const float4* s1 = (const float4*)(g_y2 + ((size_t)bs * C2V + o0 + 1) * NPTS);
    const float4* s2 = (const float4*)(g_y2 + ((size_t)bs * C2V + o0 + 2) * NPTS);
    const float4* s3 = (const float4*)(g_y2 + ((size_t)bs * C2V + o0 + 3) * NPTS);
    for (int i = t; i < NPTS / 4; i += 256) {
        float4 a = s0[i], b = s1[i], c = s2[i], d = s3[i];
        sh_v[4 * i + 0] = make_float4(fmaxf(fmaf(a.x, Ax[0], Bx[0]), 0.f), fmaxf(fmaf(b.x, Ax[1], Bx[1]), 0.f),
                                      fmaxf(fmaf(c.x, Ax[2], Bx[2]), 0.f), fmaxf(fmaf(d.x, Ax[3], Bx[3]), 0.f));
        sh_v[4 * i + 1] = make_float4(fmaxf(fmaf(a.y, Ax[0], Bx[0]), 0.f), fmaxf(fmaf(b.y, Ax[1], Bx[1]), 0.f),
                                      fmaxf(fmaf(c.y, Ax[2], Bx[2]), 0.f), fmaxf(fmaf(d.y, Ax[3], Bx[3]), 0.f));
        sh_v[4 * i + 2] = make_float4(fmaxf(fmaf(a.z, Ax[0], Bx[0]), 0.f), fmaxf(fmaf(b.z, Ax[1], Bx[1]), 0.f),
                                      fmaxf(fmaf(c.z, Ax[2], Bx[2]), 0.f), fmaxf(fmaf(d.z, Ax[3], Bx[3]), 0.f));
        sh_v[4 * i + 3] = make_float4(fmaxf(fmaf(a.w, Ax[0], Bx[0]), 0.f), fmaxf(fmaf(b.w, Ax[1], Bx[1]), 0.f),
                                      fmaxf(fmaf(c.w, Ax[2], Bx[2]), 0.f), fmaxf(fmaf(d.w, Ax[3], Bx[3]), 0.f));
    }
    if (t < 144) { float w = W3[t]; sw3p[t] = pack2(w, w); }
    __syncthreads();

    float bv = __ldg(b3);
    unsigned long long acc01 = pack2(bv, bv);
    unsigned long long acc23 = pack2(bv, bv);
    const char* vbase = (const char*)sh_v;
    const uint4* Pp = (const uint4*)(d_P) + t * 18;
#pragma unroll 3
    for (int q8 = 0; q8 < 18; q8++) {
        uint4 pv = Pp[q8];
        unsigned off[8] = { pv.x & 0xFFFFu, pv.x >> 16,
                            pv.y & 0xFFFFu, pv.y >> 16,
                            pv.z & 0xFFFFu, pv.z >> 16,
                            pv.w & 0xFFFFu, pv.w >> 16 };
#pragma unroll
        for (int jj = 0; jj < 8; jj++) {
            ulonglong2 vv = *(const ulonglong2*)(vbase + off[jj]);
            unsigned long long ww = sw3p[q8 * 8 + jj];
            FMA2(acc01, vv.x, ww);
            FMA2(acc23, vv.y, ww);
        }
    }
    float2 r01 = unpack2(acc01);
    float2 r23 = unpack2(acc23);
    float* op = out + (size_t)bs * NPTS + cb4 * 1024 + t;
    op[0]   = fmaxf(r01.x, 0.f);
    op[256] = fmaxf(r01.y, 0.f);
    op[512] = fmaxf(r23.x, 0.f);
    op[768] = fmaxf(r23.y, 0.f);
}

// ---------------- launch -----------------------------------------------------
extern "C" void kernel_launch(void* const* d_in, const int* in_sizes, int n_in,
                              void* d_out, int out_size)
{
    const float* input = (const float*)d_in[0];
    const int*   neigh = (const int*)  d_in[1];
    const float* W1    = (const float*)d_in[2];
    const float* b1    = (const float*)d_in[3];
    const float* W2    = (const float*)d_in[4];
    const float* b2    = (const float*)d_in[5];
    const float* gamma = (const float*)d_in[6];
    const float* beta  = (const float*)d_in[7];
    const float* W3    = (const float*)d_in[8];
    const float* b3    = (const float*)d_in[9];
    float* out = (float*)d_out;

    static int smem_set = 0;
    if (!smem_set) {
        cudaFuncSetAttribute(k2_stage2, cudaFuncAttributeMaxDynamicSharedMemorySize,
                             131072 + 36864 + 512);
        cudaFuncSetAttribute(k3_stage3, cudaFuncAttributeMaxDynamicSharedMemorySize,
                             65536 + 1216);
        smem_set = 1;
    }

    k1_stage1<<<(BS_TOT * NPTS) / 256, 256>>>(input, W1, b1, neigh);
    k2_stage2<<<BS_TOT * 4, 256, 131072 + 36864 + 512>>>(W2, b2);
    k3_stage3<<<BS_TOT * 4, 256, 65536 + 1216>>>(W3, b3, gamma, beta, out);
}

// round 8
// speedup vs baseline: 1.0126x; 1.0126x over previous
#include <cuda_runtime.h>
#include <cstdint>
#include <cstddef>

// Problem constants (B=8, S=24, N=4096, K=9, C1=32, C2=16)
#define BS_TOT 192
#define SDIM   24
#define NPTS   4096
#define KNB    9
#define C1V    32
#define C2V    16
#define JTOT   36864   // KNB * NPTS
#define BN_EPS 1e-5f

// ---------------- device scratch (static globals: allocation-free) ----------
__device__ __align__(16) unsigned short d_P[JTOT];  // gather byte-offsets (*8, float2)
__device__ float g_sum[SDIM * C2V];
__device__ float g_sumsq[SDIM * C2V];
// h in 4-channel-interleaved layout: g_h4[(bs*8 + qb)*NPTS + p]
__device__ float4 g_h4[(size_t)BS_TOT * 8 * NPTS];    // 96 MB
__device__ float  g_y2[(size_t)BS_TOT * C2V * NPTS];  // stage-2 out (48 MB)

// ---------------- packed f32x2 helpers (sm_103a FFMA2 path) ----------------
__device__ __forceinline__ unsigned long long pack2(float x, float y) {
    unsigned long long r;
    asm("mov.b64 %0, {%1, %2};" : "=l"(r)
        : "r"(__float_as_uint(x)), "r"(__float_as_uint(y)));
    return r;
}
__device__ __forceinline__ float2 unpack2(unsigned long long v) {
    unsigned int a, b;
    asm("mov.b64 {%0, %1}, %2;" : "=r"(a), "=r"(b) : "l"(v));
    return make_float2(__uint_as_float(a), __uint_as_float(b));
}
#define FMA2(acc, a, b) \
    asm("fma.rn.f32x2 %0, %1, %2, %0;" : "+l"(acc) : "l"(a), "l"(b))

// ---------------- K1: stage 1 conv (+ folded P-build and BN zeroing) --------
__global__ void __launch_bounds__(256) k1_stage1(
    const float* __restrict__ in, const float* __restrict__ W1,
    const float* __restrict__ b1, const int* __restrict__ neigh)
{
    __shared__ __align__(16) unsigned long long sw[KNB * 16];
    __shared__ unsigned long long sb[16];
    int t = threadIdx.x;

    // folded k0: blocks 0..143 build d_P (float2 byte offsets); BN zeroing
    int j = blockIdx.x * 256 + t;
    if (j < JTOT) {
        int n = j & (NPTS - 1);
        int k = j >> 12;
        d_P[j] = (unsigned short)(neigh[n * KNB + k] * 8);
    }
    if (j < SDIM * C2V) { g_sum[j] = 0.f; g_sumsq[j] = 0.f; }

    if (t < KNB * 16) {
        int q = t >> 4, oh = t & 15;
        sw[t] = pack2(W1[(2 * oh) * KNB + q], W1[(2 * oh + 1) * KNB + q]);
    }
    if (t < 16) sb[t] = pack2(b1[2 * t], b1[2 * t + 1]);
    __syncthreads();

    int g  = blockIdx.x * 256 + t;
    int bs = g >> 12;
    int pp = g & (NPTS - 1);
    const float* ip = in + (size_t)bs * JTOT;

    unsigned long long acc[16];
#pragma unroll
    for (int oh = 0; oh < 16; oh++) acc[oh] = sb[oh];

    int base = pp * KNB;
#pragma unroll
    for (int q = 0; q < KNB; q++) {
        int jt = base + q;
        float v = __ldg(ip + ((jt & (NPTS - 1)) * KNB) + (jt >> 12));
        unsigned long long v2 = pack2(v, v);
        const ulonglong2* w = (const ulonglong2*)(sw + q * 16);
#pragma unroll
        for (int oh2 = 0; oh2 < 8; oh2++) {
            ulonglong2 ww = w[oh2];
            FMA2(acc[2 * oh2],     v2, ww.x);
            FMA2(acc[2 * oh2 + 1], v2, ww.y);
        }
    }

    float4* hp = g_h4 + (size_t)bs * (8 * NPTS) + pp;
#pragma unroll
    for (int qb = 0; qb < 8; qb++) {
        float2 a = unpack2(acc[2 * qb]);
        float2 b = unpack2(acc[2 * qb + 1]);
        hp[qb * NPTS] = make_float4(fmaxf(a.x, 0.f), fmaxf(a.y, 0.f),
                                    fmaxf(b.x, 0.f), fmaxf(b.y, 0.f));
    }
}

// ---------------- K2: gather + GEMM, output-paired FFMA2, 2 CTA/SM ----------
// Block (bs, qb): channels 4qb..4qb+3 stored as two float2 slices.
// 256 threads: tt = t&127 (gather row), half = t>>7 (channel pair).
// Thread streams: s=0 -> p' = qb*512 + (2half)*128 + tt (channel 4qb+2half),
//                 s=1 -> +128 (channel 4qb+2half+1).
// Per tap: 1 LDS.64 gather + 4 LDS.128 weight-pairs + 2 splat MOV + 16 FFMA2.
__global__ void __launch_bounds__(256, 2) k2_stage2(
    const float* __restrict__ W2, const float* __restrict__ b2)
{
    extern __shared__ char smem[];
    float2* sh2 = (float2*)smem;                                      // 64 KB (2 x 32 KB)
    unsigned long long* sh_wp = (unsigned long long*)(smem + 65536);  // 18 KB
    float* red_s = (float*)(smem + 65536 + 18432);                    // 8*16
    float* red_q = red_s + 128;

    int blk = blockIdx.x;
    int bs  = blk >> 3;
    int qb  = blk & 7;
    int t   = threadIdx.x;
    int tt  = t & 127;
    int half = t >> 7;

    // fill: split float4 slice into two float2 slices
    const float4* hsrc = g_h4 + ((size_t)bs * 8 + qb) * NPTS;
    for (int i = t; i < NPTS; i += 256) {
        float4 v = hsrc[i];
        sh2[i]        = make_float2(v.x, v.y);
        sh2[NPTS + i] = make_float2(v.z, v.w);
    }
    // weight-pair table: sh_wp[q*8+o2] = (W2[2o2][q], W2[2o2+1][q])
    for (int i = t; i < 288 * 8; i += 256) {
        int q = i >> 3, o2 = i & 7;
        sh_wp[i] = pack2(W2[(2 * o2) * 288 + q], W2[(2 * o2 + 1) * 288 + q]);
    }
    __syncthreads();

    unsigned long long acc0[8], acc1[8];   // acc{s}[o2] = (y[s,2o2], y[s,2o2+1])
#pragma unroll
    for (int o2 = 0; o2 < 8; o2++) {
        unsigned long long bp = pack2(__ldg(b2 + 2 * o2), __ldg(b2 + 2 * o2 + 1));
        acc0[o2] = bp; acc1[o2] = bp;
    }

    const char* hb = (const char*)(sh2 + half * NPTS);
    const uint4* Pp = (const uint4*)(d_P) + tt * 36;   // row tt: 288 u16 offsets
#pragma unroll 2
    for (int q8 = 0; q8 < 36; q8++) {
        uint4 pv = Pp[q8];
        unsigned off[8] = { pv.x & 0xFFFFu, pv.x >> 16,
                            pv.y & 0xFFFFu, pv.y >> 16,
                            pv.z & 0xFFFFu, pv.z >> 16,
                            pv.w & 0xFFFFu, pv.w >> 16 };
#pragma unroll
        for (int jj = 0; jj < 8; jj++) {
            float2 h = *(const float2*)(hb + off[jj]);   // (h_c0, h_c1)
            unsigned long long h0 = pack2(h.x, h.x);
            unsigned long long h1 = pack2(h.y, h.y);
            const ulonglong2* wp = (const ulonglong2*)(sh_wp + (q8 * 8 + jj) * 8);
#pragma unroll
            for (int o4 = 0; o4 < 4; o4++) {
                ulonglong2 w = wp[o4];
                FMA2(acc0[2 * o4],     h0, w.x);
                FMA2(acc0[2 * o4 + 1], h0, w.y);
                FMA2(acc1[2 * o4],     h1, w.x);
                FMA2(acc1[2 * o4 + 1], h1, w.y);
            }
        }
    }

    // write y2 + BN partial stats
    int soff0 = (2 * half) * 128;
    float* dst = g_y2 + (size_t)bs * (C2V * NPTS) + qb * 512 + tt;
    float vsum[16], vsq[16];
#pragma unroll
    for (int o2 = 0; o2 < 8; o2++) {
        float2 f0 = unpack2(acc0[o2]);   // stream 0: outputs 2o2, 2o2+1
        float2 f1 = unpack2(acc1[o2]);   // stream 1
        dst[(2 * o2) * NPTS + soff0]           = f0.x;
        dst[(2 * o2 + 1) * NPTS + soff0]       = f0.y;
        dst[(2 * o2) * NPTS + soff0 + 128]     = f1.x;
        dst[(2 * o2 + 1) * NPTS + soff0 + 128] = f1.y;
        vsum[2 * o2]     = f0.x + f1.x;  vsq[2 * o2]     = f0.x * f0.x + f1.x * f1.x;
        vsum[2 * o2 + 1] = f0.y + f1.y;  vsq[2 * o2 + 1] = f0.y * f0.y + f1.y * f1.y;
    }

    int warp = t >> 5, lane = t & 31;
#pragma unroll
    for (int o = 0; o < 16; o++) {
        float v = vsum[o], sq = vsq[o];
#pragma unroll
        for (int off2 = 16; off2; off2 >>= 1) {
            v  += __shfl_down_sync(0xFFFFFFFFu, v,  off2);
            sq += __shfl_down_sync(0xFFFFFFFFu, sq, off2);
        }
        if (lane == 0) { red_s[warp * 16 + o] = v; red_q[warp * 16 + o] = sq; }
    }
    __syncthreads();
    if (t < 16) {
        float a = 0.f, q = 0.f;
#pragma unroll
        for (int w = 0; w < 8; w++) { a += red_s[w * 16 + t]; q += red_q[w * 16 + t]; }
        int s = bs % SDIM;
        atomicAdd(&g_sum[s * C2V + t], a);
        atomicAdd(&g_sumsq[s * C2V + t], q);
    }
}

// ---------------- K3: BN(inline)+relu, float2 slice, 2 streams --------------
// Block (bs, ob): channels c0=2ob, c1=2ob+1 as float2 slice (32 KB -> 6 CTA/SM).
// Thread t: p''_0 = ob*512 + t (ch c0), p''_1 = ob*512 + 256 + t (ch c1);
// per tap: 1 LDS.64 gather + 1 broadcast LDS.64 + 1 FFMA2.
__global__ void __launch_bounds__(256) k3_stage3(
    const float* __restrict__ W3, const float* __restrict__ b3,
    const float* __restrict__ gamma, const float* __restrict__ beta,
    float* __restrict__ out)
{
    extern __shared__ char smem3[];
    float2* sh_v = (float2*)smem3;                                   // 32 KB
    unsigned long long* sw3p = (unsigned long long*)(smem3 + 32768); // 144*8

    int blk = blockIdx.x;
    int bs  = blk >> 3;
    int ob  = blk & 7;
    int c0  = 2 * ob;
    int t   = threadIdx.x;
    int s   = bs % SDIM;

    // inline BN finalize for the two channels
    const float inv_cnt = 1.0f / (8.0f * (float)NPTS);
    float mean0 = g_sum[s * C2V + c0] * inv_cnt;
    float var0  = g_sumsq[s * C2V + c0] * inv_cnt - mean0 * mean0;
    float A0 = __ldg(gamma + c0) * rsqrtf(var0 + BN_EPS);
    float B0 = __ldg(beta + c0) - mean0 * A0;
    float mean1 = g_sum[s * C2V + c0 + 1] * inv_cnt;
    float var1  = g_sumsq[s * C2V + c0 + 1] * inv_cnt - mean1 * mean1;
    float A1 = __ldg(gamma + c0 + 1) * rsqrtf(var1 + BN_EPS);
    float B1 = __ldg(beta + c0 + 1) - mean1 * A1;

    const float4* s0 = (const float4*)(g_y2 + ((size_t)bs * C2V + c0) * NPTS);
    const float4* s1 = (const float4*)(g_y2 + ((size_t)bs * C2V + c0 + 1) * NPTS);
    for (int i = t; i < NPTS / 4; i += 256) {
        float4 a = s0[i], b = s1[i];
        sh_v[4 * i + 0] = make_float2(fmaxf(fmaf(a.x, A0, B0), 0.f), fmaxf(fmaf(b.x, A1, B1), 0.f));
        sh_v[4 * i + 1] = make_float2(fmaxf(fmaf(a.y, A0, B0), 0.f), fmaxf(fmaf(b.y, A1, B1), 0.f));
        sh_v[4 * i + 2] = make_float2(fmaxf(fmaf(a.z, A0, B0), 0.f), fmaxf(fmaf(b.z, A1, B1), 0.f));
        sh_v[4 * i + 3] = make_float2(fmaxf(fmaf(a.w, A0, B0), 0.f), fmaxf(fmaf(b.w, A1, B1), 0.f));
    }
    if (t < 144) { float w = W3[t]; sw3p[t] = pack2(w, w); }
    __syncthreads();

    float bv = __ldg(b3);
    unsigned long long acc = pack2(bv, bv);
    const char* vbase = (const char*)sh_v;
    const uint4* Pp = (const uint4*)(d_P) + t * 18;  // row t: 144 u16 offsets
#pragma unroll 3
    for (int q8 = 0; q8 < 18; q8++) {
        uint4 pv = Pp[q8];
        unsigned off[8] = { pv.x & 0xFFFFu, pv.x >> 16,
                            pv.y & 0xFFFFu, pv.y >> 16,
                            pv.z & 0xFFFFu, pv.z >> 16,
                            pv.w & 0xFFFFu, pv.w >> 16 };
#pragma unroll
        for (int jj = 0; jj < 8; jj++) {
            unsigned long long vv = *(const unsigned long long*)(vbase + off[jj]);
            FMA2(acc, vv, sw3p[q8 * 8 + jj]);
        }
    }
    float2 r = unpack2(acc);
    float* op = out + (size_t)bs * NPTS + ob * 512 + t;
    op[0]   = fmaxf(r.x, 0.f);
    op[256] = fmaxf(r.y, 0.f);
}

// ---------------- launch -----------------------------------------------------
extern "C" void kernel_launch(void* const* d_in, const int* in_sizes, int n_in,
                              void* d_out, int out_size)
{
    const float* input = (const float*)d_in[0];
    const int*   neigh = (const int*)  d_in[1];
    const float* W1    = (const float*)d_in[2];
    const float* b1    = (const float*)d_in[3];
    const float* W2    = (const float*)d_in[4];
    const float* b2    = (const float*)d_in[5];
    const float* gamma = (const float*)d_in[6];
    const float* beta  = (const float*)d_in[7];
    const float* W3    = (const float*)d_in[8];
    const float* b3    = (const float*)d_in[9];
    float* out = (float*)d_out;

    static int smem_set = 0;
    if (!smem_set) {
        cudaFuncSetAttribute(k2_stage2, cudaFuncAttributeMaxDynamicSharedMemorySize,
                             65536 + 18432 + 1024);
        cudaFuncSetAttribute(k3_stage3, cudaFuncAttributeMaxDynamicSharedMemorySize,
                             32768 + 1216);
        smem_set = 1;
    }

    k1_stage1<<<(BS_TOT * NPTS) / 256, 256>>>(input, W1, b1, neigh);
    k2_stage2<<<BS_TOT * 8, 256, 65536 + 18432 + 1024>>>(W2, b2);
    k3_stage3<<<BS_TOT * 8, 256, 32768 + 1216>>>(W3, b3, gamma, beta, out);
}

// round 10
// speedup vs baseline: 1.0776x; 1.0642x over previous
#include <cuda_runtime.h>
#include <cuda_fp16.h>
#include <cstdint>
#include <cstddef>

// Problem constants (B=8, S=24, N=4096, K=9, C1=32, C2=16)
#define BS_TOT 192
#define SDIM   24
#define NPTS   4096
#define KNB    9
#define C1V    32
#define C2V    16
#define JTOT   36864   // KNB * NPTS
#define NCOL   6144    // 192*32 columns of hT
#define BN_EPS 1e-5f

// ---------------- device scratch (static globals: allocation-free) ----------
__device__ __align__(16) unsigned short d_P2[JTOT]; // raw gather indices (0..4095)
__device__ __align__(16) unsigned short d_P3[JTOT]; // remapped float2 byte offsets for k3
__device__ float g_sum[SDIM * C2V];
__device__ float g_sumsq[SDIM * C2V];
__device__ __half g_hT[(size_t)NPTS * NCOL];        // transposed stage-1 out (48 MB)
// y2 stored REMAPPED: g_y2[bs][o][loc], loc = r*32 + c  (n = c*128 + r)
__device__ float g_y2[(size_t)BS_TOT * C2V * NPTS]; // 48 MB

// ---------------- packed f32x2 helpers (sm_103a FFMA2 path) ----------------
__device__ __forceinline__ unsigned long long pack2(float x, float y) {
    unsigned long long r;
    asm("mov.b64 %0, {%1, %2};" : "=l"(r)
        : "r"(__float_as_uint(x)), "r"(__float_as_uint(y)));
    return r;
}
__device__ __forceinline__ float2 unpack2(unsigned long long v) {
    unsigned int a, b;
    asm("mov.b64 {%0, %1}, %2;" : "=r"(a), "=r"(b) : "l"(v));
    return make_float2(__uint_as_float(a), __uint_as_float(b));
}
#define FMA2(acc, a, b) \
    asm("fma.rn.f32x2 %0, %1, %2, %0;" : "+l"(acc) : "l"(a), "l"(b))

// ---------------- K1: stage 1 conv -> fp16 transposed hT (+ P tables, BN=0) -
__global__ void __launch_bounds__(256) k1_stage1(
    const float* __restrict__ in, const float* __restrict__ W1,
    const float* __restrict__ b1, const int* __restrict__ neigh)
{
    __shared__ __align__(16) unsigned long long sw[KNB * 16];
    __shared__ unsigned long long sb[16];
    int t = threadIdx.x;

    // folded prep: first 144 blocks build both index tables; zero BN sums
    int j = blockIdx.x * 256 + t;
    if (j < JTOT) {
        int n = j & (NPTS - 1);
        int k = j >> 12;
        int idx = neigh[n * KNB + k];
        d_P2[j] = (unsigned short)idx;
        d_P3[j] = (unsigned short)((((idx & 127) << 5) + (idx >> 7)) * 8);
    }
    if (j < SDIM * C2V) { g_sum[j] = 0.f; g_sumsq[j] = 0.f; }

    if (t < KNB * 16) {
        int q = t >> 4, oh = t & 15;
        sw[t] = pack2(W1[(2 * oh) * KNB + q], W1[(2 * oh + 1) * KNB + q]);
    }
    if (t < 16) sb[t] = pack2(b1[2 * t], b1[2 * t + 1]);
    __syncthreads();

    int g  = blockIdx.x * 256 + t;
    int bs = g >> 12;
    int pp = g & (NPTS - 1);
    const float* ip = in + (size_t)bs * JTOT;

    unsigned long long acc[16];
#pragma unroll
    for (int oh = 0; oh < 16; oh++) acc[oh] = sb[oh];

    int base = pp * KNB;
#pragma unroll
    for (int q = 0; q < KNB; q++) {
        int jt = base + q;
        float v = __ldg(ip + ((jt & (NPTS - 1)) * KNB) + (jt >> 12));
        unsigned long long v2 = pack2(v, v);
        const ulonglong2* w = (const ulonglong2*)(sw + q * 16);
#pragma unroll
        for (int oh2 = 0; oh2 < 8; oh2++) {
            ulonglong2 ww = w[oh2];
            FMA2(acc[2 * oh2],     v2, ww.x);
            FMA2(acc[2 * oh2 + 1], v2, ww.y);
        }
    }

    // relu + fp16, store 32 channels = 4 x uint4 at hT[pp][bs*32]
    uint4* hp = (uint4*)(g_hT + (size_t)pp * NCOL + bs * 32);
#pragma unroll
    for (int qb = 0; qb < 4; qb++) {
        __half2 h2[4];
#pragma unroll
        for (int i = 0; i < 4; i++) {
            float2 f = unpack2(acc[4 * qb + i]);
            h2[i] = __floats2half2_rn(fmaxf(f.x, 0.f), fmaxf(f.y, 0.f));
        }
        hp[qb] = *(uint4*)h2;
    }
}

// ---------------- K2: transposed streaming GEMM + BN stats ------------------
// Block (r, ct): gather row r (uniform idx/warp), columns [ct*1024, ct*1024+1024).
// Thread t: 4 cols (one bs, channels c0..c0+3). Per tap: 1 LDS.16 idx +
// 1 LDG.64 (coalesced fp16 x4) + 8 broadcast LDS.128 weights + 32 FFMA2.
__global__ void __launch_bounds__(256, 2) k2_stage2(
    const float* __restrict__ W2, const float* __restrict__ b2)
{
    __shared__ __align__(16) unsigned long long sW[288 * 16];  // 36 KB splat pairs
    __shared__ __align__(16) unsigned short sP[292];

    int b  = blockIdx.x;
    int r  = b & 127;
    int ct = b >> 7;            // 0..5
    int t  = threadIdx.x;

    int col0 = ct * 1024 + t * 4;
    int bs   = col0 >> 5;
    int c0   = col0 & 31;

    // weight splat table: sW[q*16+o] = (W2[o][q], W2[o][q])
    for (int i = t; i < 288 * 16; i += 256) {
        int q = i >> 4, o = i & 15;
        float w = __ldg(W2 + o * 288 + q);
        sW[i] = pack2(w, w);
    }
    // FIX(R9 bug): strided fill covers all 288 entries with 256 threads
    for (int i = t; i < 288; i += 256) sP[i] = d_P2[r * 288 + i];
    if (t == 0) sP[288] = 0;   // prefetch pad
    __syncthreads();

    unsigned long long acc01[16], acc23[16];  // (col0,col1) / (col2,col3) per output
#pragma unroll
    for (int o = 0; o < 16; o++) {
        float bb = __ldg(b2 + o);
        unsigned long long bp = pack2(bb, bb);
        acc01[o] = bp; acc23[o] = bp;
    }

    const char* hTb = (const char*)g_hT + (size_t)col0 * 2;
    uint2 nxt = *(const uint2*)(hTb + (size_t)sP[0] * (NCOL * 2));
#pragma unroll 4
    for (int q = 0; q < 288; q++) {
        uint2 cur = nxt;
        nxt = *(const uint2*)(hTb + (size_t)sP[q + 1] * (NCOL * 2));
        float2 f01 = __half22float2(*(__half2*)&cur.x);
        float2 f23 = __half22float2(*(__half2*)&cur.y);
        unsigned long long H01 = pack2(f01.x, f01.y);
        unsigned long long H23 = pack2(f23.x, f23.y);
        const ulonglong2* ws = (const ulonglong2*)(sW + q * 16);
#pragma unroll
        for (int o2 = 0; o2 < 8; o2++) {
            ulonglong2 wv = ws[o2];
            FMA2(acc01[2 * o2],     H01, wv.x);
            FMA2(acc01[2 * o2 + 1], H01, wv.y);
            FMA2(acc23[2 * o2],     H23, wv.x);
            FMA2(acc23[2 * o2 + 1], H23, wv.y);
        }
    }

    // write y2 (remapped loc = r*32 + c) + BN partial sums
    float* dstb = g_y2 + (size_t)bs * (C2V * NPTS) + r * 32 + c0;
    float vsum[16], vsq[16];
#pragma unroll
    for (int o = 0; o < 16; o++) {
        float2 f01 = unpack2(acc01[o]);
        float2 f23 = unpack2(acc23[o]);
        *(float4*)(dstb + o * NPTS) = make_float4(f01.x, f01.y, f23.x, f23.y);
        vsum[o] = (f01.x + f01.y) + (f23.x + f23.y);
        vsq[o]  = (f01.x * f01.x + f01.y * f01.y) + (f23.x * f23.x + f23.y * f23.y);
    }

    // reduce within 8-lane groups (same bs), then atomic merge
    int s = bs % SDIM;
#pragma unroll
    for (int o = 0; o < 16; o++) {
        float v = vsum[o], sq = vsq[o];
#pragma unroll
        for (int off = 4; off; off >>= 1) {
            v  += __shfl_down_sync(0xFFFFFFFFu, v,  off, 8);
            sq += __shfl_down_sync(0xFFFFFFFFu, sq, off, 8);
        }
        if ((t & 7) == 0) {
            atomicAdd(&g_sum[s * C2V + o], v);
            atomicAdd(&g_sumsq[s * C2V + o], sq);
        }
    }
}

// ---------------- K3: BN(inline)+relu, float2 slice, remapped gather --------
__global__ void __launch_bounds__(256) k3_stage3(
    const float* __restrict__ W3, const float* __restrict__ b3,
    const float* __restrict__ gamma, const float* __restrict__ beta,
    float* __restrict__ out)
{
    __shared__ __align__(16) float2 sh_v[NPTS];                  // 32 KB
    __shared__ __align__(16) unsigned long long sw3p[144];

    int blk = blockIdx.x;
    int bs  = blk >> 3;
    int ob  = blk & 7;
    int c0  = 2 * ob;
    int t   = threadIdx.x;
    int s   = bs % SDIM;

    const float inv_cnt = 1.0f / (8.0f * (float)NPTS);
    float mean0 = g_sum[s * C2V + c0] * inv_cnt;
    float var0  = g_sumsq[s * C2V + c0] * inv_cnt - mean0 * mean0;
    float A0 = __ldg(gamma + c0) * rsqrtf(var0 + BN_EPS);
    float B0 = __ldg(beta + c0) - mean0 * A0;
    float mean1 = g_sum[s * C2V + c0 + 1] * inv_cnt;
    float var1  = g_sumsq[s * C2V + c0 + 1] * inv_cnt - mean1 * mean1;
    float A1 = __ldg(gamma + c0 + 1) * rsqrtf(var1 + BN_EPS);
    float B1 = __ldg(beta + c0 + 1) - mean1 * A1;

    // fill slice in stored (remapped) order — gather table d_P3 matches it
    const float4* s0 = (const float4*)(g_y2 + ((size_t)bs * C2V + c0) * NPTS);
    const float4* s1 = (const float4*)(g_y2 + ((size_t)bs * C2V + c0 + 1) * NPTS);
    for (int i = t; i < NPTS / 4; i += 256) {
        float4 a = s0[i], b = s1[i];
        sh_v[4 * i + 0] = make_float2(fmaxf(fmaf(a.x, A0, B0), 0.f), fmaxf(fmaf(b.x, A1, B1), 0.f));
        sh_v[4 * i + 1] = make_float2(fmaxf(fmaf(a.y, A0, B0), 0.f), fmaxf(fmaf(b.y, A1, B1), 0.f));
        sh_v[4 * i + 2] = make_float2(fmaxf(fmaf(a.z, A0, B0), 0.f), fmaxf(fmaf(b.z, A1, B1), 0.f));
        sh_v[4 * i + 3] = make_float2(fmaxf(fmaf(a.w, A0, B0), 0.f), fmaxf(fmaf(b.w, A1, B1), 0.f));
    }
    if (t < 144) { float w = W3[t]; sw3p[t] = pack2(w, w); }
    __syncthreads();

    float bv = __ldg(b3);
    unsigned long long acc = pack2(bv, bv);
    const char* vbase = (const char*)sh_v;
    const uint4* Pp = (const uint4*)(d_P3) + t * 18;  // row t: 144 u16 offsets
#pragma unroll 3
    for (int q8 = 0; q8 < 18; q8++) {
        uint4 pv = Pp[q8];
        unsigned off[8] = { pv.x & 0xFFFFu, pv.x >> 16,
                            pv.y & 0xFFFFu, pv.y >> 16,
                            pv.z & 0xFFFFu, pv.z >> 16,
                            pv.w & 0xFFFFu, pv.w >> 16 };
#pragma unroll
        for (int jj = 0; jj < 8; jj++) {
            unsigned long long vv = *(const unsigned long long*)(vbase + off[jj]);
            FMA2(acc, vv, sw3p[q8 * 8 + jj]);
        }
    }
    float2 rr = unpack2(acc);
    float* op = out + (size_t)bs * NPTS + ob * 512 + t;
    op[0]   = fmaxf(rr.x, 0.f);
    op[256] = fmaxf(rr.y, 0.f);
}

// ---------------- launch -----------------------------------------------------
extern "C" void kernel_launch(void* const* d_in, const int* in_sizes, int n_in,
                              void* d_out, int out_size)
{
    const float* input = (const float*)d_in[0];
    const int*   neigh = (const int*)  d_in[1];
    const float* W1    = (const float*)d_in[2];
    const float* b1    = (const float*)d_in[3];
    const float* W2    = (const float*)d_in[4];
    const float* b2    = (const float*)d_in[5];
    const float* gamma = (const float*)d_in[6];
    const float* beta  = (const float*)d_in[7];
    const float* W3    = (const float*)d_in[8];
    const float* b3    = (const float*)d_in[9];
    float* out = (float*)d_out;

    k1_stage1<<<(BS_TOT * NPTS) / 256, 256>>>(input, W1, b1, neigh);
    k2_stage2<<<768, 256>>>(W2, b2);
    k3_stage3<<<BS_TOT * 8, 256>>>(W3, b3, gamma, beta, out);
}

// round 11
// speedup vs baseline: 1.0781x; 1.0005x over previous
#include <cuda_runtime.h>
#include <cuda_fp16.h>
#include <cstdint>
#include <cstddef>

// Problem constants (B=8, S=24, N=4096, K=9, C1=32, C2=16)
#define BS_TOT 192
#define SDIM   24
#define NPTS   4096
#define KNB    9
#define C1V    32
#define C2V    16
#define JTOT   36864   // KNB * NPTS
#define NCOL   6144    // 192*32 columns of hT
#define BN_EPS 1e-5f

// ---------------- device scratch (static globals: allocation-free) ----------
__device__ __align__(16) unsigned short d_P2[JTOT]; // raw gather indices (0..4095)
__device__ __align__(16) unsigned short d_P3[JTOT]; // remapped float2 byte offsets for k3
__device__ float g_sum[SDIM * C2V];
__device__ float g_sumsq[SDIM * C2V];
__device__ __half g_hT[(size_t)NPTS * NCOL];        // transposed stage-1 out (48 MB)
// y2 stored REMAPPED: g_y2[bs][o][loc], loc = r*32 + c  (n = c*128 + r)
__device__ float g_y2[(size_t)BS_TOT * C2V * NPTS]; // 48 MB

// ---------------- packed f32x2 helpers (sm_103a FFMA2 path) ----------------
__device__ __forceinline__ unsigned long long pack2(float x, float y) {
    unsigned long long r;
    asm("mov.b64 %0, {%1, %2};" : "=l"(r)
        : "r"(__float_as_uint(x)), "r"(__float_as_uint(y)));
    return r;
}
__device__ __forceinline__ float2 unpack2(unsigned long long v) {
    unsigned int a, b;
    asm("mov.b64 {%0, %1}, %2;" : "=r"(a), "=r"(b) : "l"(v));
    return make_float2(__uint_as_float(a), __uint_as_float(b));
}
#define FMA2(acc, a, b) \
    asm("fma.rn.f32x2 %0, %1, %2, %0;" : "+l"(acc) : "l"(a), "l"(b))

// ---------------- K1: stage 1 conv -> fp16 transposed hT (+ P tables, BN=0) -
__global__ void __launch_bounds__(256) k1_stage1(
    const float* __restrict__ in, const float* __restrict__ W1,
    const float* __restrict__ b1, const int* __restrict__ neigh)
{
    __shared__ __align__(16) unsigned long long sw[KNB * 16];
    __shared__ unsigned long long sb[16];
    int t = threadIdx.x;

    // folded prep: first 144 blocks build both index tables; zero BN sums
    int j = blockIdx.x * 256 + t;
    if (j < JTOT) {
        int n = j & (NPTS - 1);
        int k = j >> 12;
        int idx = neigh[n * KNB + k];
        d_P2[j] = (unsigned short)idx;
        d_P3[j] = (unsigned short)((((idx & 127) << 5) + (idx >> 7)) * 8);
    }
    if (j < SDIM * C2V) { g_sum[j] = 0.f; g_sumsq[j] = 0.f; }

    if (t < KNB * 16) {
        int q = t >> 4, oh = t & 15;
        sw[t] = pack2(W1[(2 * oh) * KNB + q], W1[(2 * oh + 1) * KNB + q]);
    }
    if (t < 16) sb[t] = pack2(b1[2 * t], b1[2 * t + 1]);
    __syncthreads();

    int g  = blockIdx.x * 256 + t;
    int bs = g >> 12;
    int pp = g & (NPTS - 1);
    const float* ip = in + (size_t)bs * JTOT;

    unsigned long long acc[16];
#pragma unroll
    for (int oh = 0; oh < 16; oh++) acc[oh] = sb[oh];

    int base = pp * KNB;
#pragma unroll
    for (int q = 0; q < KNB; q++) {
        int jt = base + q;
        float v = __ldg(ip + ((jt & (NPTS - 1)) * KNB) + (jt >> 12));
        unsigned long long v2 = pack2(v, v);
        const ulonglong2* w = (const ulonglong2*)(sw + q * 16);
#pragma unroll
        for (int oh2 = 0; oh2 < 8; oh2++) {
            ulonglong2 ww = w[oh2];
            FMA2(acc[2 * oh2],     v2, ww.x);
            FMA2(acc[2 * oh2 + 1], v2, ww.y);
        }
    }

    // relu + fp16, store 32 channels = 4 x uint4 at hT[pp][bs*32]
    uint4* hp = (uint4*)(g_hT + (size_t)pp * NCOL + bs * 32);
#pragma unroll
    for (int qb = 0; qb < 4; qb++) {
        __half2 h2[4];
#pragma unroll
        for (int i = 0; i < 4; i++) {
            float2 f = unpack2(acc[4 * qb + i]);
            h2[i] = __floats2half2_rn(fmaxf(f.x, 0.f), fmaxf(f.y, 0.f));
        }
        hp[qb] = *(uint4*)h2;
    }
}

// ---------------- K2: transposed streaming GEMM + BN stats ------------------
// Block (r, ct): gather row r (uniform idx/warp), columns [ct*1024, ct*1024+1024).
// Thread t: 4 cols. Depth-4 LDG prefetch ring keeps MLP=4 per warp so the
// ~250-cyc L2 latency of the coalesced hT loads is fully covered.
__global__ void __launch_bounds__(256, 2) k2_stage2(
    const float* __restrict__ W2, const float* __restrict__ b2)
{
    __shared__ __align__(16) unsigned long long sW[288 * 16];  // 36 KB splat pairs
    __shared__ __align__(16) unsigned short sP[296];

    int b  = blockIdx.x;
    int r  = b & 127;
    int ct = b >> 7;            // 0..5
    int t  = threadIdx.x;

    int col0 = ct * 1024 + t * 4;
    int bs   = col0 >> 5;
    int c0   = col0 & 31;

    // weight splat table: sW[q*16+o] = (W2[o][q], W2[o][q])
    for (int i = t; i < 288 * 16; i += 256) {
        int q = i >> 4, o = i & 15;
        float w = __ldg(W2 + o * 288 + q);
        sW[i] = pack2(w, w);
    }
    for (int i = t; i < 288; i += 256) sP[i] = d_P2[r * 288 + i];
    if (t < 8) sP[288 + t] = 0;   // prefetch pad (ring reads up to sP[295])
    __syncthreads();

    unsigned long long acc01[16], acc23[16];  // (col0,col1) / (col2,col3) per output
#pragma unroll
    for (int o = 0; o < 16; o++) {
        float bb = __ldg(b2 + o);
        unsigned long long bp = pack2(bb, bb);
        acc01[o] = bp; acc23[o] = bp;
    }

    const char* hTb = (const char*)g_hT + (size_t)col0 * 2;

    // depth-4 prefetch ring
    uint2 buf[4];
#pragma unroll
    for (int i = 0; i < 4; i++)
        buf[i] = *(const uint2*)(hTb + (size_t)sP[i] * (NCOL * 2));

#pragma unroll 1
    for (int q0 = 0; q0 < 288; q0 += 4) {
#pragma unroll
        for (int u = 0; u < 4; u++) {
            uint2 cur = buf[u];
            buf[u] = *(const uint2*)(hTb + (size_t)sP[q0 + 4 + u] * (NCOL * 2));
            float2 f01 = __half22float2(*(__half2*)&cur.x);
            float2 f23 = __half22float2(*(__half2*)&cur.y);
            unsigned long long H01 = pack2(f01.x, f01.y);
            unsigned long long H23 = pack2(f23.x, f23.y);
            const ulonglong2* ws = (const ulonglong2*)(sW + (q0 + u) * 16);
#pragma unroll
            for (int o2 = 0; o2 < 8; o2++) {
                ulonglong2 wv = ws[o2];
                FMA2(acc01[2 * o2],     H01, wv.x);
                FMA2(acc01[2 * o2 + 1], H01, wv.y);
                FMA2(acc23[2 * o2],     H23, wv.x);
                FMA2(acc23[2 * o2 + 1], H23, wv.y);
            }
        }
    }

    // write y2 (remapped loc = r*32 + c) + BN partial sums
    float* dstb = g_y2 + (size_t)bs * (C2V * NPTS) + r * 32 + c0;
    float vsum[16], vsq[16];
#pragma unroll
    for (int o = 0; o < 16; o++) {
        float2 f01 = unpack2(acc01[o]);
        float2 f23 = unpack2(acc23[o]);
        *(float4*)(dstb + o * NPTS) = make_float4(f01.x, f01.y, f23.x, f23.y);
        vsum[o] = (f01.x + f01.y) + (f23.x + f23.y);
        vsq[o]  = (f01.x * f01.x + f01.y * f01.y) + (f23.x * f23.x + f23.y * f23.y);
    }

    // reduce within 8-lane groups (same bs), then atomic merge
    int s = bs % SDIM;
#pragma unroll
    for (int o = 0; o < 16; o++) {
        float v = vsum[o], sq = vsq[o];
#pragma unroll
        for (int off = 4; off; off >>= 1) {
            v  += __shfl_down_sync(0xFFFFFFFFu, v,  off, 8);
            sq += __shfl_down_sync(0xFFFFFFFFu, sq, off, 8);
        }
        if ((t & 7) == 0) {
            atomicAdd(&g_sum[s * C2V + o], v);
            atomicAdd(&g_sumsq[s * C2V + o], sq);
        }
    }
}

// ---------------- K3: BN(inline)+relu, float2 slice, remapped gather --------
__global__ void __launch_bounds__(256) k3_stage3(
    const float* __restrict__ W3, const float* __restrict__ b3,
    const float* __restrict__ gamma, const float* __restrict__ beta,
    float* __restrict__ out)
{
    __shared__ __align__(16) float2 sh_v[NPTS];                  // 32 KB
    __shared__ __align__(16) unsigned long long sw3p[144];

    int blk = blockIdx.x;
    int bs  = blk >> 3;
    int ob  = blk & 7;
    int c0  = 2 * ob;
    int t   = threadIdx.x;
    int s   = bs % SDIM;

    const float inv_cnt = 1.0f / (8.0f * (float)NPTS);
    float mean0 = g_sum[s * C2V + c0] * inv_cnt;
    float var0  = g_sumsq[s * C2V + c0] * inv_cnt - mean0 * mean0;
    float A0 = __ldg(gamma + c0) * rsqrtf(var0 + BN_EPS);
    float B0 = __ldg(beta + c0) - mean0 * A0;
    float mean1 = g_sum[s * C2V + c0 + 1] * inv_cnt;
    float var1  = g_sumsq[s * C2V + c0 + 1] * inv_cnt - mean1 * mean1;
    float A1 = __ldg(gamma + c0 + 1) * rsqrtf(var1 + BN_EPS);
    float B1 = __ldg(beta + c0 + 1) - mean1 * A1;

    // fill slice in stored (remapped) order — gather table d_P3 matches it
    const float4* s0 = (const float4*)(g_y2 + ((size_t)bs * C2V + c0) * NPTS);
    const float4* s1 = (const float4*)(g_y2 + ((size_t)bs * C2V + c0 + 1) * NPTS);
    for (int i = t; i < NPTS / 4; i += 256) {
        float4 a = s0[i], b = s1[i];
        sh_v[4 * i + 0] = make_float2(fmaxf(fmaf(a.x, A0, B0), 0.f), fmaxf(fmaf(b.x, A1, B1), 0.f));
        sh_v[4 * i + 1] = make_float2(fmaxf(fmaf(a.y, A0, B0), 0.f), fmaxf(fmaf(b.y, A1, B1), 0.f));
        sh_v[4 * i + 2] = make_float2(fmaxf(fmaf(a.z, A0, B0), 0.f), fmaxf(fmaf(b.z, A1, B1), 0.f));
        sh_v[4 * i + 3] = make_float2(fmaxf(fmaf(a.w, A0, B0), 0.f), fmaxf(fmaf(b.w, A1, B1), 0.f));
    }
    if (t < 144) { float w = W3[t]; sw3p[t] = pack2(w, w); }
    __syncthreads();

    float bv = __ldg(b3);
    unsigned long long acc = pack2(bv, bv);
    const char* vbase = (const char*)sh_v;
    const uint4* Pp = (const uint4*)(d_P3) + t * 18;  // row t: 144 u16 offsets
#pragma unroll 3
    for (int q8 = 0; q8 < 18; q8++) {
        uint4 pv = Pp[q8];
        unsigned off[8] = { pv.x & 0xFFFFu, pv.x >> 16,
                            pv.y & 0xFFFFu, pv.y >> 16,
                            pv.z & 0xFFFFu, pv.z >> 16,
                            pv.w & 0xFFFFu, pv.w >> 16 };
#pragma unroll
        for (int jj = 0; jj < 8; jj++) {
            unsigned long long vv = *(const unsigned long long*)(vbase + off[jj]);
            FMA2(acc, vv, sw3p[q8 * 8 + jj]);
        }
    }
    float2 rr = unpack2(acc);
    float* op = out + (size_t)bs * NPTS + ob * 512 + t;
    op[0]   = fmaxf(rr.x, 0.f);
    op[256] = fmaxf(rr.y, 0.f);
}

// ---------------- launch -----------------------------------------------------
extern "C" void kernel_launch(void* const* d_in, const int* in_sizes, int n_in,
                              void* d_out, int out_size)
{
    const float* input = (const float*)d_in[0];
    const int*   neigh = (const int*)  d_in[1];
    const float* W1    = (const float*)d_in[2];
    const float* b1    = (const float*)d_in[3];
    const float* W2    = (const float*)d_in[4];
    const float* b2    = (const float*)d_in[5];
    const float* gamma = (const float*)d_in[6];
    const float* beta  = (const float*)d_in[7];
    const float* W3    = (const float*)d_in[8];
    const float* b3    = (const float*)d_in[9];
    float* out = (float*)d_out;

    k1_stage1<<<(BS_TOT * NPTS) / 256, 256>>>(input, W1, b1, neigh);
    k2_stage2<<<768, 256>>>(W2, b2);
    k3_stage3<<<BS_TOT * 8, 256>>>(W3, b3, gamma, beta, out);
}

// round 12
// speedup vs baseline: 1.1126x; 1.0320x over previous
#include <cuda_runtime.h>
#include <cuda_fp16.h>
#include <cstdint>
#include <cstddef>

// Problem constants (B=8, S=24, N=4096, K=9, C1=32, C2=16)
#define BS_TOT 192
#define SDIM   24
#define NPTS   4096
#define KNB    9
#define C1V    32
#define C2V    16
#define JTOT   36864   // KNB * NPTS
#define NCOL   6144    // 192*32 columns of hT
#define BN_EPS 1e-5f

// k2 smem layout constants
#define AS_STRIDE_B 272          // 136 halfs per row (128 data + 8 pad)
#define WS_STRIDE_H 296          // halfs per W2 row (288 data + 8 pad)
#define SM_AS_BYTES (288 * AS_STRIDE_B)          // 78336
#define SM_WS_BYTES (16 * WS_STRIDE_H * 2)       // 9472
#define SM_TOTAL    (SM_AS_BYTES + SM_WS_BYTES + 288 * 2)   // + sP

// ---------------- device scratch (static globals: allocation-free) ----------
__device__ __align__(16) unsigned short d_P2[JTOT]; // raw gather indices
__device__ __align__(16) unsigned short d_P3[JTOT]; // remapped float2 byte offsets (k3)
__device__ float g_sum[SDIM * C2V];
__device__ float g_sumsq[SDIM * C2V];
__device__ __half g_hT[(size_t)NPTS * NCOL];        // transposed stage-1 out (48 MB)
// y2 stored REMAPPED: g_y2[bs][o][loc], loc = r*32 + c  (p' = c*128 + r)
__device__ float g_y2[(size_t)BS_TOT * C2V * NPTS]; // 48 MB

// ---------------- packed f32x2 helpers (k1/k3 FFMA2 path) -------------------
__device__ __forceinline__ unsigned long long pack2(float x, float y) {
    unsigned long long r;
    asm("mov.b64 %0, {%1, %2};" : "=l"(r)
        : "r"(__float_as_uint(x)), "r"(__float_as_uint(y)));
    return r;
}
__device__ __forceinline__ float2 unpack2(unsigned long long v) {
    unsigned int a, b;
    asm("mov.b64 {%0, %1}, %2;" : "=r"(a), "=r"(b) : "l"(v));
    return make_float2(__uint_as_float(a), __uint_as_float(b));
}
#define FMA2(acc, a, b) \
    asm("fma.rn.f32x2 %0, %1, %2, %0;" : "+l"(acc) : "l"(a), "l"(b))

// ---------------- mma helpers -----------------------------------------------
__device__ __forceinline__ void ldsm_x4(unsigned &r0, unsigned &r1,
                                        unsigned &r2, unsigned &r3, unsigned a) {
    asm volatile("ldmatrix.sync.aligned.m8n8.x4.shared.b16 {%0,%1,%2,%3},[%4];"
                 : "=r"(r0), "=r"(r1), "=r"(r2), "=r"(r3) : "r"(a));
}
__device__ __forceinline__ void ldsm_x2t(unsigned &r0, unsigned &r1, unsigned a) {
    asm volatile("ldmatrix.sync.aligned.m8n8.x2.trans.shared.b16 {%0,%1},[%2];"
                 : "=r"(r0), "=r"(r1) : "r"(a));
}
__device__ __forceinline__ void mma16816(float &d0, float &d1, float &d2, float &d3,
                                         unsigned a0, unsigned a1, unsigned a2, unsigned a3,
                                         unsigned b0, unsigned b1) {
    asm volatile("mma.sync.aligned.m16n8k16.row.col.f32.f16.f16.f32 "
                 "{%0,%1,%2,%3},{%4,%5,%6,%7},{%8,%9},{%0,%1,%2,%3};"
                 : "+f"(d0), "+f"(d1), "+f"(d2), "+f"(d3)
                 : "r"(a0), "r"(a1), "r"(a2), "r"(a3), "r"(b0), "r"(b1));
}

// ---------------- K1: stage 1 conv -> fp16 transposed hT (+ P tables, BN=0) -
__global__ void __launch_bounds__(256) k1_stage1(
    const float* __restrict__ in, const float* __restrict__ W1,
    const float* __restrict__ b1, const int* __restrict__ neigh)
{
    __shared__ __align__(16) unsigned long long sw[KNB * 16];
    __shared__ unsigned long long sb[16];
    int t = threadIdx.x;

    int j = blockIdx.x * 256 + t;
    if (j < JTOT) {
        int n = j & (NPTS - 1);
        int k = j >> 12;
        int idx = neigh[n * KNB + k];
        d_P2[j] = (unsigned short)idx;
        d_P3[j] = (unsigned short)((((idx & 127) << 5) + (idx >> 7)) * 8);
    }
    if (j < SDIM * C2V) { g_sum[j] = 0.f; g_sumsq[j] = 0.f; }

    if (t < KNB * 16) {
        int q = t >> 4, oh = t & 15;
        sw[t] = pack2(W1[(2 * oh) * KNB + q], W1[(2 * oh + 1) * KNB + q]);
    }
    if (t < 16) sb[t] = pack2(b1[2 * t], b1[2 * t + 1]);
    __syncthreads();

    int g  = blockIdx.x * 256 + t;
    int bs = g >> 12;
    int pp = g & (NPTS - 1);
    const float* ip = in + (size_t)bs * JTOT;

    unsigned long long acc[16];
#pragma unroll
    for (int oh = 0; oh < 16; oh++) acc[oh] = sb[oh];

    int base = pp * KNB;
#pragma unroll
    for (int q = 0; q < KNB; q++) {
        int jt = base + q;
        float v = __ldg(ip + ((jt & (NPTS - 1)) * KNB) + (jt >> 12));
        unsigned long long v2 = pack2(v, v);
        const ulonglong2* w = (const ulonglong2*)(sw + q * 16);
#pragma unroll
        for (int oh2 = 0; oh2 < 8; oh2++) {
            ulonglong2 ww = w[oh2];
            FMA2(acc[2 * oh2],     v2, ww.x);
            FMA2(acc[2 * oh2 + 1], v2, ww.y);
        }
    }

    uint4* hp = (uint4*)(g_hT + (size_t)pp * NCOL + bs * 32);
#pragma unroll
    for (int qb = 0; qb < 4; qb++) {
        __half2 h2[4];
#pragma unroll
        for (int i = 0; i < 4; i++) {
            float2 f = unpack2(acc[4 * qb + i]);
            h2[i] = __floats2half2_rn(fmaxf(f.x, 0.f), fmaxf(f.y, 0.f));
        }
        hp[qb] = *(uint4*)h2;
    }
}

// ---------------- K2: tensor-core GEMM per (r, col-tile) + BN stats ---------
// Block (ct, r): D[o=16, col=128] = W2[16,288] x A[288,128], where A row q is
// hT row P2[r*288+q], cols [ct*128, ct*128+128). A staged in smem (272B rows),
// W2 fp16 in smem (592B rows). mma m16n8k16: A-frag = W2 (ldmatrix.x4),
// B-frag = staged tile (ldmatrix.x2.trans). 8 warps x 16 cols each.
__global__ void __launch_bounds__(256, 2) k2_mma(
    const float* __restrict__ W2, const float* __restrict__ b2)
{
    extern __shared__ char sm[];
    __half* As = (__half*)sm;
    __half* Ws = (__half*)(sm + SM_AS_BYTES);
    unsigned short* sP = (unsigned short*)(sm + SM_AS_BYTES + SM_WS_BYTES);

    int blk = blockIdx.x;
    int r   = blk & 127;
    int ct  = blk >> 7;          // 0..47
    int t   = threadIdx.x;
    int lane = t & 31, w = t >> 5;

    for (int i = t; i < 288; i += 256) sP[i] = d_P2[r * 288 + i];
    for (int i = t; i < 16 * 288; i += 256) {
        int o = i / 288, q = i - o * 288;
        Ws[o * WS_STRIDE_H + q] = __float2half(__ldg(W2 + o * 288 + q));
    }
    __syncthreads();

    // stage 288 gathered rows (256 B each, coalesced)
    const char* hbase = (const char*)g_hT + (size_t)ct * 128 * 2;
    for (int i = t; i < 288 * 16; i += 256) {
        int q = i >> 4, off = i & 15;
        uint4 v = *(const uint4*)(hbase + (size_t)sP[q] * (NCOL * 2) + off * 16);
        *(uint4*)((char*)As + q * AS_STRIDE_B + off * 16) = v;
    }
    __syncthreads();

    unsigned as_u = (unsigned)__cvta_generic_to_shared(As);
    unsigned ws_u = (unsigned)__cvta_generic_to_shared(Ws);

    int g = lane >> 2;
    float d[2][4];
    {
        float bi0 = __ldg(b2 + g), bi1 = __ldg(b2 + g + 8);
        d[0][0] = bi0; d[0][1] = bi0; d[0][2] = bi1; d[0][3] = bi1;
        d[1][0] = bi0; d[1][1] = bi0; d[1][2] = bi1; d[1][3] = bi1;
    }

    // A (W2): rows o = lane%16, k-seg = (lane>>4)*8
    unsigned aBase = ws_u + (lane % 16) * (WS_STRIDE_H * 2) + ((lane >> 4) * 8) * 2;
    // B (staged): rows k = lane%16 (+k0), cols n0 = w*16 (+8 for tile1)
    unsigned bBase = as_u + (lane % 16) * AS_STRIDE_B + (w * 16) * 2;

#pragma unroll
    for (int ks = 0; ks < 18; ks++) {
        unsigned a0, a1, a2, a3, b0, b1, b2r, b3r;
        ldsm_x4(a0, a1, a2, a3, aBase + ks * 16 * 2);
        ldsm_x2t(b0, b1,  bBase + ks * 16 * AS_STRIDE_B);
        ldsm_x2t(b2r, b3r, bBase + ks * 16 * AS_STRIDE_B + 16);
        mma16816(d[0][0], d[0][1], d[0][2], d[0][3], a0, a1, a2, a3, b0, b1);
        mma16816(d[1][0], d[1][1], d[1][2], d[1][3], a0, a1, a2, a3, b2r, b3r);
    }

    // epilogue: D[m=o][n=col]; thread holds o=g,g+8; cols colL, colL+1 (+8 tile1)
    int colL = w * 16 + (lane & 3) * 2;
    int colG = ct * 128 + colL;
    int bs = colG >> 5;
    int c  = colG & 31;
    float* base0 = g_y2 + (size_t)bs * (C2V * NPTS) + r * 32;
    *(float2*)(base0 + g * NPTS + c)           = make_float2(d[0][0], d[0][1]);
    *(float2*)(base0 + (g + 8) * NPTS + c)     = make_float2(d[0][2], d[0][3]);
    *(float2*)(base0 + g * NPTS + c + 8)       = make_float2(d[1][0], d[1][1]);
    *(float2*)(base0 + (g + 8) * NPTS + c + 8) = make_float2(d[1][2], d[1][3]);

    // BN partial sums: reduce cols within each quad, atomics from quad leaders
    float s0 = d[0][0] + d[0][1] + d[1][0] + d[1][1];
    float q0 = d[0][0] * d[0][0] + d[0][1] * d[0][1] + d[1][0] * d[1][0] + d[1][1] * d[1][1];
    float s1 = d[0][2] + d[0][3] + d[1][2] + d[1][3];
    float q1 = d[0][2] * d[0][2] + d[0][3] * d[0][3] + d[1][2] * d[1][2] + d[1][3] * d[1][3];
    s0 += __shfl_down_sync(0xFFFFFFFFu, s0, 1, 4);
    s0 += __shfl_down_sync(0xFFFFFFFFu, s0, 2, 4);
    q0 += __shfl_down_sync(0xFFFFFFFFu, q0, 1, 4);
    q0 += __shfl_down_sync(0xFFFFFFFFu, q0, 2, 4);
    s1 += __shfl_down_sync(0xFFFFFFFFu, s1, 1, 4);
    s1 += __shfl_down_sync(0xFFFFFFFFu, s1, 2, 4);
    q1 += __shfl_down_sync(0xFFFFFFFFu, q1, 1, 4);
    q1 += __shfl_down_sync(0xFFFFFFFFu, q1, 2, 4);
    if ((lane & 3) == 0) {
        int s = bs % SDIM;
        atomicAdd(&g_sum[s * C2V + g], s0);
        atomicAdd(&g_sumsq[s * C2V + g], q0);
        atomicAdd(&g_sum[s * C2V + g + 8], s1);
        atomicAdd(&g_sumsq[s * C2V + g + 8], q1);
    }
}

// ---------------- K3: BN(inline)+relu, float2 slice, remapped gather --------
__global__ void __launch_bounds__(256) k3_stage3(
    const float* __restrict__ W3, const float* __restrict__ b3,
    const float* __restrict__ gamma, const float* __restrict__ beta,
    float* __restrict__ out)
{
    __shared__ __align__(16) float2 sh_v[NPTS];                  // 32 KB
    __shared__ __align__(16) unsigned long long sw3p[144];

    int blk = blockIdx.x;
    int bs  = blk >> 3;
    int ob  = blk & 7;
    int c0  = 2 * ob;
    int t   = threadIdx.x;
    int s   = bs % SDIM;

    const float inv_cnt = 1.0f / (8.0f * (float)NPTS);
    float mean0 = g_sum[s * C2V + c0] * inv_cnt;
    float var0  = g_sumsq[s * C2V + c0] * inv_cnt - mean0 * mean0;
    float A0 = __ldg(gamma + c0) * rsqrtf(var0 + BN_EPS);
    float B0 = __ldg(beta + c0) - mean0 * A0;
    float mean1 = g_sum[s * C2V + c0 + 1] * inv_cnt;
    float var1  = g_sumsq[s * C2V + c0 + 1] * inv_cnt - mean1 * mean1;
    float A1 = __ldg(gamma + c0 + 1) * rsqrtf(var1 + BN_EPS);
    float B1 = __ldg(beta + c0 + 1) - mean1 * A1;

    const float4* s0 = (const float4*)(g_y2 + ((size_t)bs * C2V + c0) * NPTS);
    const float4* s1 = (const float4*)(g_y2 + ((size_t)bs * C2V + c0 + 1) * NPTS);
    for (int i = t; i < NPTS / 4; i += 256) {
        float4 a = s0[i], b = s1[i];
        sh_v[4 * i + 0] = make_float2(fmaxf(fmaf(a.x, A0, B0), 0.f), fmaxf(fmaf(b.x, A1, B1), 0.f));
        sh_v[4 * i + 1] = make_float2(fmaxf(fmaf(a.y, A0, B0), 0.f), fmaxf(fmaf(b.y, A1, B1), 0.f));
        sh_v[4 * i + 2] = make_float2(fmaxf(fmaf(a.z, A0, B0), 0.f), fmaxf(fmaf(b.z, A1, B1), 0.f));
        sh_v[4 * i + 3] = make_float2(fmaxf(fmaf(a.w, A0, B0), 0.f), fmaxf(fmaf(b.w, A1, B1), 0.f));
    }
    if (t < 144) { float w = W3[t]; sw3p[t] = pack2(w, w); }
    __syncthreads();

    float bv = __ldg(b3);
    unsigned long long acc = pack2(bv, bv);
    const char* vbase = (const char*)sh_v;
    const uint4* Pp = (const uint4*)(d_P3) + t * 18;
#pragma unroll 3
    for (int q8 = 0; q8 < 18; q8++) {
        uint4 pv = Pp[q8];
        unsigned off[8] = { pv.x & 0xFFFFu, pv.x >> 16,
                            pv.y & 0xFFFFu, pv.y >> 16,
                            pv.z & 0xFFFFu, pv.z >> 16,
                            pv.w & 0xFFFFu, pv.w >> 16 };
#pragma unroll
        for (int jj = 0; jj < 8; jj++) {
            unsigned long long vv = *(const unsigned long long*)(vbase + off[jj]);
            FMA2(acc, vv, sw3p[q8 * 8 + jj]);
        }
    }
    float2 rr = unpack2(acc);
    float* op = out + (size_t)bs * NPTS + ob * 512 + t;
    op[0]   = fmaxf(rr.x, 0.f);
    op[256] = fmaxf(rr.y, 0.f);
}

// ---------------- launch -----------------------------------------------------
extern "C" void kernel_launch(void* const* d_in, const int* in_sizes, int n_in,
                              void* d_out, int out_size)
{
    const float* input = (const float*)d_in[0];
    const int*   neigh = (const int*)  d_in[1];
    const float* W1    = (const float*)d_in[2];
    const float* b1    = (const float*)d_in[3];
    const float* W2    = (const float*)d_in[4];
    const float* b2    = (const float*)d_in[5];
    const float* gamma = (const float*)d_in[6];
    const float* beta  = (const float*)d_in[7];
    const float* W3    = (const float*)d_in[8];
    const float* b3    = (const float*)d_in[9];
    float* out = (float*)d_out;

    static int smem_set = 0;
    if (!smem_set) {
        cudaFuncSetAttribute(k2_mma, cudaFuncAttributeMaxDynamicSharedMemorySize,
                             SM_TOTAL);
        smem_set = 1;
    }

    k1_stage1<<<(BS_TOT * NPTS) / 256, 256>>>(input, W1, b1, neigh);
    k2_mma<<<48 * 128, 256, SM_TOTAL>>>(W2, b2);
    k3_stage3<<<BS_TOT * 8, 256>>>(W3, b3, gamma, beta, out);
}

// round 13
// speedup vs baseline: 1.1763x; 1.0572x over previous
#include <cuda_runtime.h>
#include <cuda_fp16.h>
#include <cstdint>
#include <cstddef>

// Problem constants (B=8, S=24, N=4096, K=9, C1=32, C2=16)
#define BS_TOT 192
#define SDIM   24
#define NPTS   4096
#define KNB    9
#define C1V    32
#define C2V    16
#define JTOT   36864   // KNB * NPTS
#define NCOL   6144    // 192*32 columns of hT
#define BN_EPS 1e-5f

// k2 smem layout constants
#define AS_STRIDE_B 272          // 136 halfs per row (128 data + 8 pad)
#define WS_STRIDE_B 592          // 296 halfs per W2 row (288 data + 8 pad)
#define SM_AS_BYTES (288 * AS_STRIDE_B)          // 78336 (16B aligned)
#define SM_WS_BYTES (16 * WS_STRIDE_B)           // 9472
#define SM_TOTAL    (SM_AS_BYTES + SM_WS_BYTES)

// ---------------- device scratch (static globals: allocation-free) ----------
__device__ __align__(16) unsigned short d_P2[JTOT]; // raw gather indices
__device__ __align__(16) unsigned short d_P3[JTOT]; // remapped float2 byte offsets (k3)
__device__ __align__(16) __half g_W2h[16 * 288];    // fp16 W2 (converted once)
__device__ float g_sum[SDIM * C2V];
__device__ float g_sumsq[SDIM * C2V];
__device__ __half g_hT[(size_t)NPTS * NCOL];        // transposed stage-1 out (48 MB)
// y2 stored REMAPPED: g_y2[bs][o][loc], loc = r*32 + c  (p' = c*128 + r)
__device__ float g_y2[(size_t)BS_TOT * C2V * NPTS]; // 48 MB

// ---------------- packed f32x2 helpers (k1/k3 FFMA2 path) -------------------
__device__ __forceinline__ unsigned long long pack2(float x, float y) {
    unsigned long long r;
    asm("mov.b64 %0, {%1, %2};" : "=l"(r)
        : "r"(__float_as_uint(x)), "r"(__float_as_uint(y)));
    return r;
}
__device__ __forceinline__ float2 unpack2(unsigned long long v) {
    unsigned int a, b;
    asm("mov.b64 {%0, %1}, %2;" : "=r"(a), "=r"(b) : "l"(v));
    return make_float2(__uint_as_float(a), __uint_as_float(b));
}
#define FMA2(acc, a, b) \
    asm("fma.rn.f32x2 %0, %1, %2, %0;" : "+l"(acc) : "l"(a), "l"(b))

// ---------------- mma helpers -----------------------------------------------
__device__ __forceinline__ void ldsm_x4(unsigned &r0, unsigned &r1,
                                        unsigned &r2, unsigned &r3, unsigned a) {
    asm volatile("ldmatrix.sync.aligned.m8n8.x4.shared.b16 {%0,%1,%2,%3},[%4];"
                 : "=r"(r0), "=r"(r1), "=r"(r2), "=r"(r3) : "r"(a));
}
__device__ __forceinline__ void ldsm_x2t(unsigned &r0, unsigned &r1, unsigned a) {
    asm volatile("ldmatrix.sync.aligned.m8n8.x2.trans.shared.b16 {%0,%1},[%2];"
                 : "=r"(r0), "=r"(r1) : "r"(a));
}
__device__ __forceinline__ void mma16816(float &d0, float &d1, float &d2, float &d3,
                                         unsigned a0, unsigned a1, unsigned a2, unsigned a3,
                                         unsigned b0, unsigned b1) {
    asm volatile("mma.sync.aligned.m16n8k16.row.col.f32.f16.f16.f32 "
                 "{%0,%1,%2,%3},{%4,%5,%6,%7},{%8,%9},{%0,%1,%2,%3};"
                 : "+f"(d0), "+f"(d1), "+f"(d2), "+f"(d3)
                 : "r"(a0), "r"(a1), "r"(a2), "r"(a3), "r"(b0), "r"(b1));
}

// ---------------- K1: stage 1 conv -> fp16 hT (+ P tables, W2h, BN=0) -------
__global__ void __launch_bounds__(256) k1_stage1(
    const float* __restrict__ in, const float* __restrict__ W1,
    const float* __restrict__ b1, const int* __restrict__ neigh,
    const float* __restrict__ W2)
{
    __shared__ __align__(16) unsigned long long sw[KNB * 16];
    __shared__ unsigned long long sb[16];
    int t = threadIdx.x;

    int j = blockIdx.x * 256 + t;
    if (j < JTOT) {
        int n = j & (NPTS - 1);
        int k = j >> 12;
        int idx = neigh[n * KNB + k];
        d_P2[j] = (unsigned short)idx;
        d_P3[j] = (unsigned short)((((idx & 127) << 5) + (idx >> 7)) * 8);
    }
    if (j < 16 * 288) g_W2h[j] = __float2half(__ldg(W2 + j));
    if (j < SDIM * C2V) { g_sum[j] = 0.f; g_sumsq[j] = 0.f; }

    if (t < KNB * 16) {
        int q = t >> 4, oh = t & 15;
        sw[t] = pack2(W1[(2 * oh) * KNB + q], W1[(2 * oh + 1) * KNB + q]);
    }
    if (t < 16) sb[t] = pack2(b1[2 * t], b1[2 * t + 1]);
    __syncthreads();

    int g  = blockIdx.x * 256 + t;
    int bs = g >> 12;
    int pp = g & (NPTS - 1);
    const float* ip = in + (size_t)bs * JTOT;

    unsigned long long acc[16];
#pragma unroll
    for (int oh = 0; oh < 16; oh++) acc[oh] = sb[oh];

    int base = pp * KNB;
#pragma unroll
    for (int q = 0; q < KNB; q++) {
        int jt = base + q;
        float v = __ldg(ip + ((jt & (NPTS - 1)) * KNB) + (jt >> 12));
        unsigned long long v2 = pack2(v, v);
        const ulonglong2* w = (const ulonglong2*)(sw + q * 16);
#pragma unroll
        for (int oh2 = 0; oh2 < 8; oh2++) {
            ulonglong2 ww = w[oh2];
            FMA2(acc[2 * oh2],     v2, ww.x);
            FMA2(acc[2 * oh2 + 1], v2, ww.y);
        }
    }

    uint4* hp = (uint4*)(g_hT + (size_t)pp * NCOL + bs * 32);
#pragma unroll
    for (int qb = 0; qb < 4; qb++) {
        __half2 h2[4];
#pragma unroll
        for (int i = 0; i < 4; i++) {
            float2 f = unpack2(acc[4 * qb + i]);
            h2[i] = __floats2half2_rn(fmaxf(f.x, 0.f), fmaxf(f.y, 0.f));
        }
        hp[qb] = *(uint4*)h2;
    }
}

// ---------------- K2: tensor-core GEMM per (r, col-tile), store-only --------
// Block (ct, r): D[o=16, col=128] = W2[16,288] x A[288,128]; A row q is hT row
// P2[r*288+q], cols [ct*128, +128). No atomics, no reductions — stats in k2b.
__global__ void __launch_bounds__(256, 2) k2_mma(const float* __restrict__ b2)
{
    extern __shared__ char sm[];
    __half* As = (__half*)sm;
    __half* Ws = (__half*)(sm + SM_AS_BYTES);

    int blk = blockIdx.x;
    int r   = blk & 127;
    int ct  = blk >> 7;          // 0..47
    int t   = threadIdx.x;
    int lane = t & 31, w = t >> 5;

    // stage W2h (9216 B, padded rows of 592 B): 576 uint4 copies
    {
        const uint4* wsrc = (const uint4*)g_W2h;
        uint4* wdst = (uint4*)Ws;
        for (int i = t; i < 576; i += 256) {
            int row = i / 36, col = i - row * 36;
            wdst[row * 37 + col] = wsrc[i];
        }
    }
    // stage 288 gathered rows (256 B each, coalesced; P2 via broadcast LDG)
    const char* hbase = (const char*)g_hT + (size_t)ct * 256;
    const unsigned short* Prow = d_P2 + r * 288;
    for (int i = t; i < 288 * 16; i += 256) {
        int q = i >> 4, off = i & 15;
        int row = __ldg(Prow + q);
        *(uint4*)((char*)As + q * AS_STRIDE_B + off * 16) =
            *(const uint4*)(hbase + (size_t)row * (NCOL * 2) + off * 16);
    }
    __syncthreads();

    unsigned as_u = (unsigned)__cvta_generic_to_shared(As);
    unsigned ws_u = (unsigned)__cvta_generic_to_shared(Ws);

    int g = lane >> 2;
    float d[2][4];
    {
        float bi0 = __ldg(b2 + g), bi1 = __ldg(b2 + g + 8);
        d[0][0] = bi0; d[0][1] = bi0; d[0][2] = bi1; d[0][3] = bi1;
        d[1][0] = bi0; d[1][1] = bi0; d[1][2] = bi1; d[1][3] = bi1;
    }

    unsigned aBase = ws_u + (lane % 16) * WS_STRIDE_B + ((lane >> 4) * 8) * 2;
    unsigned bBase = as_u + (lane % 16) * AS_STRIDE_B + (w * 16) * 2;

#pragma unroll
    for (int ks = 0; ks < 18; ks++) {
        unsigned a0, a1, a2, a3, b0, b1, b2r, b3r;
        ldsm_x4(a0, a1, a2, a3, aBase + ks * 16 * 2);
        ldsm_x2t(b0, b1,  bBase + ks * 16 * AS_STRIDE_B);
        ldsm_x2t(b2r, b3r, bBase + ks * 16 * AS_STRIDE_B + 16);
        mma16816(d[0][0], d[0][1], d[0][2], d[0][3], a0, a1, a2, a3, b0, b1);
        mma16816(d[1][0], d[1][1], d[1][2], d[1][3], a0, a1, a2, a3, b2r, b3r);
    }

    // epilogue: plain stores, nothing else
    int colL = w * 16 + (lane & 3) * 2;
    int colG = ct * 128 + colL;
    int bs = colG >> 5;
    int c  = colG & 31;
    float* base0 = g_y2 + (size_t)bs * (C2V * NPTS) + r * 32;
    *(float2*)(base0 + g * NPTS + c)           = make_float2(d[0][0], d[0][1]);
    *(float2*)(base0 + (g + 8) * NPTS + c)     = make_float2(d[0][2], d[0][3]);
    *(float2*)(base0 + g * NPTS + c + 8)       = make_float2(d[1][0], d[1][1]);
    *(float2*)(base0 + (g + 8) * NPTS + c + 8) = make_float2(d[1][2], d[1][3]);
}

// ---------------- K2b: BN stats from y2 (coalesced, few atomics) ------------
// Block = one bs; warp w handles output channel o=w: sums its contiguous
// 16 KB row. 192 blocks x 32 atomics total.
__global__ void __launch_bounds__(512) k2b_stats()
{
    int bs = blockIdx.x;
    int w  = threadIdx.x >> 5;
    int lane = threadIdx.x & 31;
    const float4* src = (const float4*)(g_y2 + ((size_t)bs * C2V + w) * NPTS);
    float s = 0.f, q = 0.f;
#pragma unroll 4
    for (int i = lane; i < NPTS / 4; i += 32) {
        float4 v = src[i];
        s += (v.x + v.y) + (v.z + v.w);
        q += (v.x * v.x + v.y * v.y) + (v.z * v.z + v.w * v.w);
    }
#pragma unroll
    for (int off = 16; off; off >>= 1) {
        s += __shfl_down_sync(0xFFFFFFFFu, s, off);
        q += __shfl_down_sync(0xFFFFFFFFu, q, off);
    }
    if (lane == 0) {
        int ss = bs % SDIM;
        atomicAdd(&g_sum[ss * C2V + w], s);
        atomicAdd(&g_sumsq[ss * C2V + w], q);
    }
}

// ---------------- K3: BN(inline)+relu, float2 slice, remapped gather --------
__global__ void __launch_bounds__(256) k3_stage3(
    const float* __restrict__ W3, const float* __restrict__ b3,
    const float* __restrict__ gamma, const float* __restrict__ beta,
    float* __restrict__ out)
{
    __shared__ __align__(16) float2 sh_v[NPTS];                  // 32 KB
    __shared__ __align__(16) unsigned long long sw3p[144];

    int blk = blockIdx.x;
    int bs  = blk >> 3;
    int ob  = blk & 7;
    int c0  = 2 * ob;
    int t   = threadIdx.x;
    int s   = bs % SDIM;

    const float inv_cnt = 1.0f / (8.0f * (float)NPTS);
    float mean0 = g_sum[s * C2V + c0] * inv_cnt;
    float var0  = g_sumsq[s * C2V + c0] * inv_cnt - mean0 * mean0;
    float A0 = __ldg(gamma + c0) * rsqrtf(var0 + BN_EPS);
    float B0 = __ldg(beta + c0) - mean0 * A0;
    float mean1 = g_sum[s * C2V + c0 + 1] * inv_cnt;
    float var1  = g_sumsq[s * C2V + c0 + 1] * inv_cnt - mean1 * mean1;
    float A1 = __ldg(gamma + c0 + 1) * rsqrtf(var1 + BN_EPS);
    float B1 = __ldg(beta + c0 + 1) - mean1 * A1;

    const float4* s0 = (const float4*)(g_y2 + ((size_t)bs * C2V + c0) * NPTS);
    const float4* s1 = (const float4*)(g_y2 + ((size_t)bs * C2V + c0 + 1) * NPTS);
    for (int i = t; i < NPTS / 4; i += 256) {
        float4 a = s0[i], b = s1[i];
        sh_v[4 * i + 0] = make_float2(fmaxf(fmaf(a.x, A0, B0), 0.f), fmaxf(fmaf(b.x, A1, B1), 0.f));
        sh_v[4 * i + 1] = make_float2(fmaxf(fmaf(a.y, A0, B0), 0.f), fmaxf(fmaf(b.y, A1, B1), 0.f));
        sh_v[4 * i + 2] = make_float2(fmaxf(fmaf(a.z, A0, B0), 0.f), fmaxf(fmaf(b.z, A1, B1), 0.f));
        sh_v[4 * i + 3] = make_float2(fmaxf(fmaf(a.w, A0, B0), 0.f), fmaxf(fmaf(b.w, A1, B1), 0.f));
    }
    if (t < 144) { float w = W3[t]; sw3p[t] = pack2(w, w); }
    __syncthreads();

    float bv = __ldg(b3);
    unsigned long long acc = pack2(bv, bv);
    const char* vbase = (const char*)sh_v;
    const uint4* Pp = (const uint4*)(d_P3) + t * 18;
#pragma unroll 3
    for (int q8 = 0; q8 < 18; q8++) {
        uint4 pv = Pp[q8];
        unsigned off[8] = { pv.x & 0xFFFFu, pv.x >> 16,
                            pv.y & 0xFFFFu, pv.y >> 16,
                            pv.z & 0xFFFFu, pv.z >> 16,
                            pv.w & 0xFFFFu, pv.w >> 16 };
#pragma unroll
        for (int jj = 0; jj < 8; jj++) {
            unsigned long long vv = *(const unsigned long long*)(vbase + off[jj]);
            FMA2(acc, vv, sw3p[q8 * 8 + jj]);
        }
    }
    float2 rr = unpack2(acc);
    float* op = out + (size_t)bs * NPTS + ob * 512 + t;
    op[0]   = fmaxf(rr.x, 0.f);
    op[256] = fmaxf(rr.y, 0.f);
}

// ---------------- launch -----------------------------------------------------
extern "C" void kernel_launch(void* const* d_in, const int* in_sizes, int n_in,
                              void* d_out, int out_size)
{
    const float* input = (const float*)d_in[0];
    const int*   neigh = (const int*)  d_in[1];
    const float* W1    = (const float*)d_in[2];
    const float* b1    = (const float*)d_in[3];
    const float* W2    = (const float*)d_in[4];
    const float* b2    = (const float*)d_in[5];
    const float* gamma = (const float*)d_in[6];
    const float* beta  = (const float*)d_in[7];
    const float* W3    = (const float*)d_in[8];
    const float* b3    = (const float*)d_in[9];
    float* out = (float*)d_out;

    static int smem_set = 0;
    if (!smem_set) {
        cudaFuncSetAttribute(k2_mma, cudaFuncAttributeMaxDynamicSharedMemorySize,
                             SM_TOTAL);
        smem_set = 1;
    }

    k1_stage1<<<(BS_TOT * NPTS) / 256, 256>>>(input, W1, b1, neigh, W2);
    k2_mma<<<48 * 128, 256, SM_TOTAL>>>(b2);
    k2b_stats<<<BS_TOT, 512>>>();
    k3_stage3<<<BS_TOT * 8, 256>>>(W3, b3, gamma, beta, out);
}

// round 15
// speedup vs baseline: 1.7528x; 1.4901x over previous
#include <cuda_runtime.h>
#include <cuda_fp16.h>
#include <cstdint>
#include <cstddef>

// Problem constants (B=8, S=24, N=4096, K=9, C1=32, C2=16)
#define BS_TOT 192
#define SDIM   24
#define NPTS   4096
#define KNB    9
#define C1V    32
#define C2V    16
#define JTOT   36864   // KNB * NPTS
#define NCOL   6144    // 192*32 columns of hT
#define BN_EPS 1e-5f

// k2 smem layout: As = 288 rows x 256 B (XOR-swizzled), Ws = 16 rows x 592 B
#define SM_AS_BYTES (288 * 256)     // 73728
#define SM_WS_BYTES (16 * 592)      // 9472
#define SM_TOTAL    (SM_AS_BYTES + SM_WS_BYTES)

// ---------------- device scratch (static globals: allocation-free) ----------
__device__ __align__(16) unsigned short d_P2[JTOT]; // raw gather indices
__device__ __align__(16) unsigned short d_P3[JTOT]; // remapped 8B offsets (k3)
__device__ __align__(16) __half g_W2h[16 * 288];    // fp16 W2 (converted once)
__device__ float g_sum[SDIM * C2V];
__device__ float g_sumsq[SDIM * C2V];
__device__ __half g_hT[(size_t)NPTS * NCOL];        // transposed stage-1 out (48 MB)
// y2 stored REMAPPED: g_y2[bs][o][loc], loc = r*32 + c  (p' = c*128 + r)
__device__ float g_y2[(size_t)BS_TOT * C2V * NPTS]; // 48 MB

// ---------------- packed f32x2 helpers (k1/k3 FFMA2 path) -------------------
__device__ __forceinline__ unsigned long long pack2(float x, float y) {
    unsigned long long r;
    asm("mov.b64 %0, {%1, %2};" : "=l"(r)
        : "r"(__float_as_uint(x)), "r"(__float_as_uint(y)));
    return r;
}
__device__ __forceinline__ float2 unpack2(unsigned long long v) {
    unsigned int a, b;
    asm("mov.b64 {%0, %1}, %2;" : "=r"(a), "=r"(b) : "l"(v));
    return make_float2(__uint_as_float(a), __uint_as_float(b));
}
#define FMA2(acc, a, b) \
    asm("fma.rn.f32x2 %0, %1, %2, %0;" : "+l"(acc) : "l"(a), "l"(b))

// ---------------- async-copy + mma helpers ----------------------------------
__device__ __forceinline__ void cp16(unsigned dst, const void* src) {
    asm volatile("cp.async.cg.shared.global [%0], [%1], 16;" :: "r"(dst), "l"(src));
}
__device__ __forceinline__ void cp_commit_wait() {
    asm volatile("cp.async.commit_group;");
    asm volatile("cp.async.wait_group 0;" ::: "memory");
}
__device__ __forceinline__ void ldsm_x4(unsigned &r0, unsigned &r1,
                                        unsigned &r2, unsigned &r3, unsigned a) {
    asm volatile("ldmatrix.sync.aligned.m8n8.x4.shared.b16 {%0,%1,%2,%3},[%4];"
                 : "=r"(r0), "=r"(r1), "=r"(r2), "=r"(r3) : "r"(a));
}
__device__ __forceinline__ void ldsm_x4t(unsigned &r0, unsigned &r1,
                                         unsigned &r2, unsigned &r3, unsigned a) {
    asm volatile("ldmatrix.sync.aligned.m8n8.x4.trans.shared.b16 {%0,%1,%2,%3},[%4];"
                 : "=r"(r0), "=r"(r1), "=r"(r2), "=r"(r3) : "r"(a));
}
__device__ __forceinline__ void mma16816(float &d0, float &d1, float &d2, float &d3,
                                         unsigned a0, unsigned a1, unsigned a2, unsigned a3,
                                         unsigned b0, unsigned b1) {
    asm volatile("mma.sync.aligned.m16n8k16.row.col.f32.f16.f16.f32 "
                 "{%0,%1,%2,%3},{%4,%5,%6,%7},{%8,%9},{%0,%1,%2,%3};"
                 : "+f"(d0), "+f"(d1), "+f"(d2), "+f"(d3)
                 : "r"(a0), "r"(a1), "r"(a2), "r"(a3), "r"(b0), "r"(b1));
}

// ---------------- K1: stage 1 conv -> fp16 hT (+ P tables, W2h, BN=0) -------
__global__ void __launch_bounds__(256) k1_stage1(
    const float* __restrict__ in, const float* __restrict__ W1,
    const float* __restrict__ b1, const int* __restrict__ neigh,
    const float* __restrict__ W2)
{
    __shared__ __align__(16) unsigned long long sw[KNB * 16];
    __shared__ unsigned long long sb[16];
    int t = threadIdx.x;

    int j = blockIdx.x * 256 + t;
    if (j < JTOT) {
        int n = j & (NPTS - 1);
        int k = j >> 12;
        int idx = neigh[n * KNB + k];
        d_P2[j] = (unsigned short)idx;
        d_P3[j] = (unsigned short)((((idx & 127) << 5) + (idx >> 7)) * 8);
    }
    if (j < 16 * 288) g_W2h[j] = __float2half(__ldg(W2 + j));
    if (j < SDIM * C2V) { g_sum[j] = 0.f; g_sumsq[j] = 0.f; }

    if (t < KNB * 16) {
        int q = t >> 4, oh = t & 15;
        sw[t] = pack2(W1[(2 * oh) * KNB + q], W1[(2 * oh + 1) * KNB + q]);
    }
    if (t < 16) sb[t] = pack2(b1[2 * t], b1[2 * t + 1]);
    __syncthreads();

    int g  = blockIdx.x * 256 + t;
    int bs = g >> 12;
    int pp = g & (NPTS - 1);
    const float* ip = in + (size_t)bs * JTOT;

    unsigned long long acc[16];
#pragma unroll
    for (int oh = 0; oh < 16; oh++) acc[oh] = sb[oh];

    int base = pp * KNB;
#pragma unroll
    for (int q = 0; q < KNB; q++) {
        int jt = base + q;
        float v = __ldg(ip + ((jt & (NPTS - 1)) * KNB) + (jt >> 12));
        unsigned long long v2 = pack2(v, v);
        const ulonglong2* w = (const ulonglong2*)(sw + q * 16);
#pragma unroll
        for (int oh2 = 0; oh2 < 8; oh2++) {
            ulonglong2 ww = w[oh2];
            FMA2(acc[2 * oh2],     v2, ww.x);
            FMA2(acc[2 * oh2 + 1], v2, ww.y);
        }
    }

    uint4* hp = (uint4*)(g_hT + (size_t)pp * NCOL + bs * 32);
#pragma unroll
    for (int qb = 0; qb < 4; qb++) {
        __half2 h2[4];
#pragma unroll
        for (int i = 0; i < 4; i++) {
            float2 f = unpack2(acc[4 * qb + i]);
            h2[i] = __floats2half2_rn(fmaxf(f.x, 0.f), fmaxf(f.y, 0.f));
        }
        hp[qb] = *(uint4*)h2;
    }
}

// ---------------- K2: tensor-core GEMM, cp.async + XOR swizzle --------------
// Block (ct, r): D[o=16, col=128] = W2[16,288] x A[288,128]; A row q is hT row
// P2[r*288+q], cols [ct*128, +128), stored swizzled: unit u -> u ^ (q&15).
__global__ void __launch_bounds__(256, 2) k2_mma(const float* __restrict__ b2)
{
    extern __shared__ char sm[];
    unsigned as_u = (unsigned)__cvta_generic_to_shared(sm);
    unsigned ws_u = as_u + SM_AS_BYTES;

    int blk = blockIdx.x;
    int r   = blk & 127;
    int ct  = blk >> 7;          // 0..47
    int t   = threadIdx.x;
    int lane = t & 31, w = t >> 5;

    // stage W2h (9216 B in 592 B-stride rows) via cp.async
    for (int i = t; i < 576; i += 256) {
        int row = i / 36, col = i - row * 36;
        cp16(ws_u + row * 592 + col * 16, (const char*)g_W2h + i * 16);
    }
    // stage 288 gathered rows (256 B each, coalesced) via cp.async, swizzled
    const char* hbase = (const char*)g_hT + (size_t)ct * 256;
    const unsigned short* Prow = d_P2 + r * 288;
    for (int i = t; i < 288 * 16; i += 256) {
        int q = i >> 4, o = i & 15;
        int row = __ldg(Prow + q);
        cp16(as_u + q * 256 + ((o ^ (q & 15)) << 4),
             hbase + (size_t)row * (NCOL * 2) + o * 16);
    }
    cp_commit_wait();
    __syncthreads();

    int g = lane >> 2;
    float d[2][4];
    {
        float bi0 = __ldg(b2 + g), bi1 = __ldg(b2 + g + 8);
        d[0][0] = bi0; d[0][1] = bi0; d[0][2] = bi1; d[0][3] = bi1;
        d[1][0] = bi0; d[1][1] = bi0; d[1][2] = bi1; d[1][3] = bi1;
    }

    int lr = lane & 15;
    unsigned aBase = ws_u + lr * 592 + ((lane >> 4) * 8) * 2;
    // B: lanes 0-15 -> tile0 (u=w*2), lanes 16-31 -> tile1 (u=w*2+1); swizzled
    unsigned bBase = as_u + lr * 256 + (((w * 2 + (lane >> 4)) ^ lr) << 4);

#pragma unroll
    for (int ks = 0; ks < 18; ks++) {
        unsigned a0, a1, a2, a3, b0, b1, b2r, b3r;
        ldsm_x4(a0, a1, a2, a3, aBase + ks * 32);
        ldsm_x4t(b0, b1, b2r, b3r, bBase + ks * 4096);
        mma16816(d[0][0], d[0][1], d[0][2], d[0][3], a0, a1, a2, a3, b0, b1);
        mma16816(d[1][0], d[1][1], d[1][2], d[1][3], a0, a1, a2, a3, b2r, b3r);
    }

    // epilogue: plain stores
    int colL = w * 16 + (lane & 3) * 2;
    int colG = ct * 128 + colL;
    int bs = colG >> 5;
    int c  = colG & 31;
    float* base0 = g_y2 + (size_t)bs * (C2V * NPTS) + r * 32;
    *(float2*)(base0 + g * NPTS + c)           = make_float2(d[0][0], d[0][1]);
    *(float2*)(base0 + (g + 8) * NPTS + c)     = make_float2(d[0][2], d[0][3]);
    *(float2*)(base0 + g * NPTS + c + 8)       = make_float2(d[1][0], d[1][1]);
    *(float2*)(base0 + (g + 8) * NPTS + c + 8) = make_float2(d[1][2], d[1][3]);
}

// ---------------- K2b: BN stats from y2 (coalesced, few atomics) ------------
__global__ void __launch_bounds__(512) k2b_stats()
{
    int bs = blockIdx.x;
    int w  = threadIdx.x >> 5;
    int lane = threadIdx.x & 31;
    const float4* src = (const float4*)(g_y2 + ((size_t)bs * C2V + w) * NPTS);
    float s = 0.f, q = 0.f;
#pragma unroll 4
    for (int i = lane; i < NPTS / 4; i += 32) {
        float4 v = src[i];
        s += (v.x + v.y) + (v.z + v.w);
        q += (v.x * v.x + v.y * v.y) + (v.z * v.z + v.w * v.w);
    }
#pragma unroll
    for (int off = 16; off; off >>= 1) {
        s += __shfl_down_sync(0xFFFFFFFFu, s, off);
        q += __shfl_down_sync(0xFFFFFFFFu, q, off);
    }
    if (lane == 0) {
        int ss = bs % SDIM;
        atomicAdd(&g_sum[ss * C2V + w], s);
        atomicAdd(&g_sumsq[ss * C2V + w], q);
    }
}

// ---------------- K3: BN+relu -> half4 slice, 4-channel fp16 gather ---------
// Block (bs, cg): channels c0=4cg..c0+3 normalized into half4 smem (8 B/point,
// 32 KB). Thread t: outputs p'' = (c0+i)*256 + t, i=0..3; all share gather
// row t. Per tap: ONE random LDS.64 covers 4 channels (half the crossbar
// traffic of the float2 version).
__global__ void __launch_bounds__(256) k3_stage3(
    const float* __restrict__ W3, const float* __restrict__ b3,
    const float* __restrict__ gamma, const float* __restrict__ beta,
    float* __restrict__ out)
{
    __shared__ __align__(16) unsigned long long sh_v[NPTS];      // 32 KB half4
    __shared__ __align__(16) unsigned long long sw3p[144];

    int blk = blockIdx.x;
    int bs  = blk >> 2;
    int cg  = blk & 3;
    int c0  = 4 * cg;
    int t   = threadIdx.x;
    int s   = bs % SDIM;

    const float inv_cnt = 1.0f / (8.0f * (float)NPTS);
    float A[4], Bb[4];
#pragma unroll
    for (int i = 0; i < 4; i++) {
        int c = c0 + i;
        float mean = g_sum[s * C2V + c] * inv_cnt;
        float var  = g_sumsq[s * C2V + c] * inv_cnt - mean * mean;
        A[i]  = __ldg(gamma + c) * rsqrtf(var + BN_EPS);
        Bb[i] = __ldg(beta + c) - mean * A[i];
    }

    const float4* s0 = (const float4*)(g_y2 + ((size_t)bs * C2V + c0) * NPTS);
    const float4* s1 = (const float4*)(g_y2 + ((size_t)bs * C2V + c0 + 1) * NPTS);
    const float4* s2 = (const float4*)(g_y2 + ((size_t)bs * C2V + c0 + 2) * NPTS);
    const float4* s3 = (const float4*)(g_y2 + ((size_t)bs * C2V + c0 + 3) * NPTS);
    for (int i = t; i < NPTS / 4; i += 256) {
        float4 a = s0[i], b = s1[i], c = s2[i], d = s3[i];
        float va[4] = { a.x, a.y, a.z, a.w };
        float vb[4] = { b.x, b.y, b.z, b.w };
        float vc[4] = { c.x, c.y, c.z, c.w };
        float vd[4] = { d.x, d.y, d.z, d.w };
#pragma unroll
        for (int e = 0; e < 4; e++) {
            __half2 lo = __floats2half2_rn(fmaxf(fmaf(va[e], A[0], Bb[0]), 0.f),
                                           fmaxf(fmaf(vb[e], A[1], Bb[1]), 0.f));
            __half2 hi = __floats2half2_rn(fmaxf(fmaf(vc[e], A[2], Bb[2]), 0.f),
                                           fmaxf(fmaf(vd[e], A[3], Bb[3]), 0.f));
            unsigned lo_u = *(unsigned*)&lo, hi_u = *(unsigned*)&hi;
            sh_v[4 * i + e] = ((unsigned long long)hi_u << 32) | lo_u;
        }
    }
    if (t < 144) { float w = W3[t]; sw3p[t] = pack2(w, w); }
    __syncthreads();

    float bv = __ldg(b3);
    unsigned long long acc01 = pack2(bv, bv);
    unsigned long long acc23 = pack2(bv, bv);
    const char* vbase = (const char*)sh_v;
    const uint4* Pp = (const uint4*)(d_P3) + t * 18;
#pragma unroll 3
    for (int q8 = 0; q8 < 18; q8++) {
        uint4 pv = Pp[q8];
        unsigned off[8] = { pv.x & 0xFFFFu, pv.x >> 16,
                            pv.y & 0xFFFFu, pv.y >> 16,
                            pv.z & 0xFFFFu, pv.z >> 16,
                            pv.w & 0xFFFFu, pv.w >> 16 };
#pragma unroll
        for (int jj = 0; jj < 8; jj++) {
            unsigned long long vv = *(const unsigned long long*)(vbase + off[jj]);
            unsigned lo_u = (unsigned)vv, hi_u = (unsigned)(vv >> 32);
            float2 f01 = __half22float2(*(__half2*)&lo_u);
            float2 f23 = __half22float2(*(__half2*)&hi_u);
            unsigned long long ww = sw3p[q8 * 8 + jj];
            FMA2(acc01, pack2(f01.x, f01.y), ww);
            FMA2(acc23, pack2(f23.x, f23.y), ww);
        }
    }
    float2 r01 = unpack2(acc01);
    float2 r23 = unpack2(acc23);
    float* op = out + (size_t)bs * NPTS + c0 * 256 + t;
    op[0]   = fmaxf(r01.x, 0.f);
    op[256] = fmaxf(r01.y, 0.f);
    op[512] = fmaxf(r23.x, 0.f);
    op[768] = fmaxf(r23.y, 0.f);
}

// ---------------- launch -----------------------------------------------------
extern "C" void kernel_launch(void* const* d_in, const int* in_sizes, int n_in,
                              void* d_out, int out_size)
{
    const float* input = (const float*)d_in[0];
    const int*   neigh = (const int*)  d_in[1];
    const float* W1    = (const float*)d_in[2];
    const float* b1    = (const float*)d_in[3];
    const float* W2    = (const float*)d_in[4];
    const float* b2    = (const float*)d_in[5];
    const float* gamma = (const float*)d_in[6];
    const float* beta  = (const float*)d_in[7];
    const float* W3    = (const float*)d_in[8];
    const float* b3    = (const float*)d_in[9];
    float* out = (float*)d_out;

    static int smem_set = 0;
    if (!smem_set) {
        cudaFuncSetAttribute(k2_mma, cudaFuncAttributeMaxDynamicSharedMemorySize,
                             SM_TOTAL);
        smem_set = 1;
    }

    k1_stage1<<<(BS_TOT * NPTS) / 256, 256>>>(input, W1, b1, neigh, W2);
    k2_mma<<<48 * 128, 256, SM_TOTAL>>>(b2);
    k2b_stats<<<BS_TOT, 512>>>();
    k3_stage3<<<BS_TOT * 4, 256>>>(W3, b3, gamma, beta, out);
}

// round 16
// speedup vs baseline: 1.8166x; 1.0364x over previous
#include <cuda_runtime.h>
#include <cuda_fp16.h>
#include <cstdint>
#include <cstddef>

// Problem constants (B=8, S=24, N=4096, K=9, C1=32, C2=16)
#define BS_TOT 192
#define SDIM   24
#define NPTS   4096
#define KNB    9
#define C1V    32
#define C2V    16
#define JTOT   36864   // KNB * NPTS
#define NCOL   6144    // 192*32 columns of hT
#define NC3    3072    // 192*16 columns of yT3
#define BN_EPS 1e-5f

// k2 smem layout: As = 288 rows x 256 B (XOR-swizzled), Ws = 16 rows x 592 B
#define SM_AS_BYTES (288 * 256)     // 73728
#define SM_WS_BYTES (16 * 592)      // 9472
#define SM_TOTAL    (SM_AS_BYTES + SM_WS_BYTES)

// ---------------- device scratch (static globals: allocation-free) ----------
__device__ __align__(16) unsigned short d_P2[JTOT]; // raw gather indices
__device__ __align__(16) unsigned short d_P3[JTOT]; // remapped loc indices (k3)
__device__ __align__(16) __half g_W2h[16 * 288];    // fp16 W2 (converted once)
__device__ float g_sum[SDIM * C2V];
__device__ float g_sumsq[SDIM * C2V];
__device__ __half g_hT[(size_t)NPTS * NCOL];        // transposed stage-1 out (48 MB)
// stage-2 out, transposed fp16: g_yT3[loc][bs*16+o], loc = r*32+c (p' = c*128+r)
__device__ __half g_yT3[(size_t)NPTS * NC3];        // 24 MB

// ---------------- packed f32x2 helpers (k1 FFMA2 path) ----------------------
__device__ __forceinline__ unsigned long long pack2(float x, float y) {
    unsigned long long r;
    asm("mov.b64 %0, {%1, %2};" : "=l"(r)
        : "r"(__float_as_uint(x)), "r"(__float_as_uint(y)));
    return r;
}
__device__ __forceinline__ float2 unpack2(unsigned long long v) {
    unsigned int a, b;
    asm("mov.b64 {%0, %1}, %2;" : "=r"(a), "=r"(b) : "l"(v));
    return make_float2(__uint_as_float(a), __uint_as_float(b));
}
#define FMA2(acc, a, b) \
    asm("fma.rn.f32x2 %0, %1, %2, %0;" : "+l"(acc) : "l"(a), "l"(b))

// ---------------- async-copy + mma helpers ----------------------------------
__device__ __forceinline__ void cp16(unsigned dst, const void* src) {
    asm volatile("cp.async.cg.shared.global [%0], [%1], 16;" :: "r"(dst), "l"(src));
}
__device__ __forceinline__ void cp_commit() {
    asm volatile("cp.async.commit_group;");
}
__device__ __forceinline__ void ldsm_x4(unsigned &r0, unsigned &r1,
                                        unsigned &r2, unsigned &r3, unsigned a) {
    asm volatile("ldmatrix.sync.aligned.m8n8.x4.shared.b16 {%0,%1,%2,%3},[%4];"
                 : "=r"(r0), "=r"(r1), "=r"(r2), "=r"(r3) : "r"(a));
}
__device__ __forceinline__ void ldsm_x4t(unsigned &r0, unsigned &r1,
                                         unsigned &r2, unsigned &r3, unsigned a) {
    asm volatile("ldmatrix.sync.aligned.m8n8.x4.trans.shared.b16 {%0,%1,%2,%3},[%4];"
                 : "=r"(r0), "=r"(r1), "=r"(r2), "=r"(r3) : "r"(a));
}
__device__ __forceinline__ void mma16816(float &d0, float &d1, float &d2, float &d3,
                                         unsigned a0, unsigned a1, unsigned a2, unsigned a3,
                                         unsigned b0, unsigned b1) {
    asm volatile("mma.sync.aligned.m16n8k16.row.col.f32.f16.f16.f32 "
                 "{%0,%1,%2,%3},{%4,%5,%6,%7},{%8,%9},{%0,%1,%2,%3};"
                 : "+f"(d0), "+f"(d1), "+f"(d2), "+f"(d3)
                 : "r"(a0), "r"(a1), "r"(a2), "r"(a3), "r"(b0), "r"(b1));
}

// ---------------- K1: stage 1 conv -> fp16 hT (+ P tables, W2h, BN=0) -------
__global__ void __launch_bounds__(256) k1_stage1(
    const float* __restrict__ in, const float* __restrict__ W1,
    const float* __restrict__ b1, const int* __restrict__ neigh,
    const float* __restrict__ W2)
{
    __shared__ __align__(16) unsigned long long sw[KNB * 16];
    __shared__ unsigned long long sb[16];
    int t = threadIdx.x;

    int j = blockIdx.x * 256 + t;
    if (j < JTOT) {
        int n = j & (NPTS - 1);
        int k = j >> 12;
        int idx = neigh[n * KNB + k];
        d_P2[j] = (unsigned short)idx;
        d_P3[j] = (unsigned short)(((idx & 127) << 5) + (idx >> 7));  // raw loc
    }
    if (j < 16 * 288) g_W2h[j] = __float2half(__ldg(W2 + j));
    if (j < SDIM * C2V) { g_sum[j] = 0.f; g_sumsq[j] = 0.f; }

    if (t < KNB * 16) {
        int q = t >> 4, oh = t & 15;
        sw[t] = pack2(W1[(2 * oh) * KNB + q], W1[(2 * oh + 1) * KNB + q]);
    }
    if (t < 16) sb[t] = pack2(b1[2 * t], b1[2 * t + 1]);
    __syncthreads();

    int g  = blockIdx.x * 256 + t;
    int bs = g >> 12;
    int pp = g & (NPTS - 1);
    const float* ip = in + (size_t)bs * JTOT;

    unsigned long long acc[16];
#pragma unroll
    for (int oh = 0; oh < 16; oh++) acc[oh] = sb[oh];

    int base = pp * KNB;
#pragma unroll
    for (int q = 0; q < KNB; q++) {
        int jt = base + q;
        float v = __ldg(ip + ((jt & (NPTS - 1)) * KNB) + (jt >> 12));
        unsigned long long v2 = pack2(v, v);
        const ulonglong2* w = (const ulonglong2*)(sw + q * 16);
#pragma unroll
        for (int oh2 = 0; oh2 < 8; oh2++) {
            ulonglong2 ww = w[oh2];
            FMA2(acc[2 * oh2],     v2, ww.x);
            FMA2(acc[2 * oh2 + 1], v2, ww.y);
        }
    }

    uint4* hp = (uint4*)(g_hT + (size_t)pp * NCOL + bs * 32);
#pragma unroll
    for (int qb = 0; qb < 4; qb++) {
        __half2 h2[4];
#pragma unroll
        for (int i = 0; i < 4; i++) {
            float2 f = unpack2(acc[4 * qb + i]);
            h2[i] = __floats2half2_rn(fmaxf(f.x, 0.f), fmaxf(f.y, 0.f));
        }
        hp[qb] = *(uint4*)h2;
    }
}

// ---------------- K2: tensor-core GEMM, pipelined cp.async, fp16 yT3 out ----
// Block (ct, r): D[o=16, col=128] = W2[16,288] x A[288,128]; A row q is hT row
// P2[r*288+q], cols [ct*128,+128), swizzled u -> u ^ (q&15). Two-phase
// cp.async wait overlaps 2nd-half staging behind 1st-half MMA. Epilogue:
// smem transpose -> coalesced fp16 stores into yT3[loc][bs*16+o].
__global__ void __launch_bounds__(256, 2) k2_mma(const float* __restrict__ b2)
{
    extern __shared__ char sm[];
    unsigned as_u = (unsigned)__cvta_generic_to_shared(sm);
    unsigned ws_u = as_u + SM_AS_BYTES;

    int blk = blockIdx.x;
    int r   = blk & 127;
    int ct  = blk >> 7;          // 0..47
    int t   = threadIdx.x;
    int lane = t & 31, w = t >> 5;

    // group 0: W2h (9216 B in 592 B-stride rows)
    for (int i = t; i < 576; i += 256) {
        int row = i / 36, col = i - row * 36;
        cp16(ws_u + row * 592 + col * 16, (const char*)g_W2h + i * 16);
    }
    cp_commit();
    // groups 1..18: A chunks of 16 q-rows each (iteration k covers q in [16k,16k+16))
    const char* hbase = (const char*)g_hT + (size_t)ct * 256;
    const unsigned short* Prow = d_P2 + r * 288;
#pragma unroll 1
    for (int k = 0; k < 18; k++) {
        int i = k * 256 + t;
        int q = i >> 4, o = i & 15;
        int row = __ldg(Prow + q);
        cp16(as_u + q * 256 + ((o ^ (q & 15)) << 4),
             hbase + (size_t)row * (NCOL * 2) + o * 16);
        cp_commit();
    }

    int g = lane >> 2;
    float d[2][4];
    {
        float bi0 = __ldg(b2 + g), bi1 = __ldg(b2 + g + 8);
        d[0][0] = bi0; d[0][1] = bi0; d[0][2] = bi1; d[0][3] = bi1;
        d[1][0] = bi0; d[1][1] = bi0; d[1][2] = bi1; d[1][3] = bi1;
    }

    int lr = lane & 15;
    unsigned aBase = ws_u + lr * 592 + ((lane >> 4) * 8) * 2;
    unsigned bBase = as_u + lr * 256 + (((w * 2 + (lane >> 4)) ^ lr) << 4);

    // phase 1: wait for W2 + chunks 0..8 (pending <= 9), mma ks 0..8
    asm volatile("cp.async.wait_group 9;" ::: "memory");
    __syncthreads();
#pragma unroll
    for (int ks = 0; ks < 9; ks++) {
        unsigned a0, a1, a2, a3, b0, b1, b2r, b3r;
        ldsm_x4(a0, a1, a2, a3, aBase + ks * 32);
        ldsm_x4t(b0, b1, b2r, b3r, bBase + ks * 4096);
        mma16816(d[0][0], d[0][1], d[0][2], d[0][3], a0, a1, a2, a3, b0, b1);
        mma16816(d[1][0], d[1][1], d[1][2], d[1][3], a0, a1, a2, a3, b2r, b3r);
    }
    // phase 2
    asm volatile("cp.async.wait_group 0;" ::: "memory");
    __syncthreads();
#pragma unroll
    for (int ks = 9; ks < 18; ks++) {
        unsigned a0, a1, a2, a3, b0, b1, b2r, b3r;
        ldsm_x4(a0, a1, a2, a3, aBase + ks * 32);
        ldsm_x4t(b0, b1, b2r, b3r, bBase + ks * 4096);
        mma16816(d[0][0], d[0][1], d[0][2], d[0][3], a0, a1, a2, a3, b0, b1);
        mma16816(d[1][0], d[1][1], d[1][2], d[1][3], a0, a1, a2, a3, b2r, b3r);
    }

    // epilogue: transpose through smem (reuse As), then coalesced fp16 stores
    __syncthreads();
    __half* sT = (__half*)sm;    // [c(32)][bsl(4)][o(16)] = 2048 halfs = 4 KB
    {
        int colL = w * 16 + (lane & 3) * 2;
        int c   = colL & 31;
        int bsl = colL >> 5;
        int bo  = bsl * 16;
        sT[(c)     * 64 + bo + g]     = __float2half(d[0][0]);
        sT[(c + 1) * 64 + bo + g]     = __float2half(d[0][1]);
        sT[(c)     * 64 + bo + g + 8] = __float2half(d[0][2]);
        sT[(c + 1) * 64 + bo + g + 8] = __float2half(d[0][3]);
        sT[(c + 8) * 64 + bo + g]     = __float2half(d[1][0]);
        sT[(c + 9) * 64 + bo + g]     = __float2half(d[1][1]);
        sT[(c + 8) * 64 + bo + g + 8] = __float2half(d[1][2]);
        sT[(c + 9) * 64 + bo + g + 8] = __float2half(d[1][3]);
    }
    __syncthreads();
    {
        int rowc = t >> 3, seg = t & 7;   // 32 rows x 128 B
        *(uint4*)(g_yT3 + (size_t)(r * 32 + rowc) * NC3 + ct * 64 + seg * 8) =
            *(const uint4*)(sT + rowc * 64 + seg * 8);
    }
}

// ---------------- K2b: BN stats from yT3 (coalesced fp16, fp32 accum) -------
__global__ void __launch_bounds__(256) k2b_stats()
{
    __shared__ float red[8][8][4];
    int bs = blockIdx.x;
    int t  = threadIdx.x;
    int op = t & 7;        // o pair: o = 2op, 2op+1
    int grp = t >> 3;      // 32 groups over loc

    float s0 = 0.f, s1 = 0.f, q0 = 0.f, q1 = 0.f;
    const __half* base = g_yT3 + bs * 16 + op * 2;
#pragma unroll 4
    for (int loc = grp; loc < NPTS; loc += 32) {
        __half2 v = *(const __half2*)(base + (size_t)loc * NC3);
        float2 f = __half22float2(v);
        s0 += f.x; s1 += f.y; q0 += f.x * f.x; q1 += f.y * f.y;
    }
    // lanes {l, l+8, l+16, l+24} share op
    s0 += __shfl_down_sync(0xFFFFFFFFu, s0, 16);
    s0 += __shfl_down_sync(0xFFFFFFFFu, s0, 8);
    s1 += __shfl_down_sync(0xFFFFFFFFu, s1, 16);
    s1 += __shfl_down_sync(0xFFFFFFFFu, s1, 8);
    q0 += __shfl_down_sync(0xFFFFFFFFu, q0, 16);
    q0 += __shfl_down_sync(0xFFFFFFFFu, q0, 8);
    q1 += __shfl_down_sync(0xFFFFFFFFu, q1, 16);
    q1 += __shfl_down_sync(0xFFFFFFFFu, q1, 8);
    int wp = t >> 5, l = t & 31;
    if (l < 8) { red[wp][l][0] = s0; red[wp][l][1] = s1; red[wp][l][2] = q0; red[wp][l][3] = q1; }
    __syncthreads();
    if (t < 8) {
        float S0 = 0.f, S1 = 0.f, Q0 = 0.f, Q1 = 0.f;
#pragma unroll
        for (int wq = 0; wq < 8; wq++) {
            S0 += red[wq][t][0]; S1 += red[wq][t][1];
            Q0 += red[wq][t][2]; Q1 += red[wq][t][3];
        }
        int ss = bs % SDIM;
        atomicAdd(&g_sum[ss * C2V + 2 * t],     S0);
        atomicAdd(&g_sum[ss * C2V + 2 * t + 1], S1);
        atomicAdd(&g_sumsq[ss * C2V + 2 * t],     Q0);
        atomicAdd(&g_sumsq[ss * C2V + 2 * t + 1], Q1);
    }
}

// ---------------- K3: transposed streaming stage-3 ---------------------------
// Block (r2, ct): gather row r2 (uniform per warp), cols [ct*1024,+1024) of
// yT3 (col = bs*16+o; o IS the output channel). Thread: 4 cols (same bs),
// per tap: ONE coalesced LDG.64 + inline BN+relu + 4 FMA. No random smem.
__global__ void __launch_bounds__(256) k3_stage3(
    const float* __restrict__ W3, const float* __restrict__ b3,
    const float* __restrict__ gamma, const float* __restrict__ beta,
    float* __restrict__ out)
{
    __shared__ unsigned short sP3[160];
    __shared__ float sw3[144];

    int blk = blockIdx.x;
    int r2  = blk & 255;
    int ct  = blk >> 8;          // 0..2
    int t   = threadIdx.x;

    if (t < 144) { sP3[t] = d_P3[r2 * 144 + t]; sw3[t] = __ldg(W3 + t); }
    else if (t < 160) sP3[t] = 0;

    int col0 = ct * 1024 + t * 4;
    int bs   = col0 >> 4;
    int o0   = col0 & 15;        // in {0,4,8,12}
    int s    = bs % SDIM;

    const float inv_cnt = 1.0f / (8.0f * (float)NPTS);
    float A[4], Bb[4];
#pragma unroll
    for (int i = 0; i < 4; i++) {
        int o = o0 + i;
        float mean = g_sum[s * C2V + o] * inv_cnt;
        float var  = g_sumsq[s * C2V + o] * inv_cnt - mean * mean;
        A[i]  = __ldg(gamma + o) * rsqrtf(var + BN_EPS);
        Bb[i] = __ldg(beta + o) - mean * A[i];
    }
    __syncthreads();

    const char* base2 = (const char*)(g_yT3 + col0);
    float acc[4] = { 0.f, 0.f, 0.f, 0.f };

    uint2 buf[4];
#pragma unroll
    for (int i = 0; i < 4; i++)
        buf[i] = *(const uint2*)(base2 + (size_t)sP3[i] * (NC3 * 2));

#pragma unroll 2
    for (int q0 = 0; q0 < 144; q0 += 4) {
#pragma unroll
        for (int u = 0; u < 4; u++) {
            uint2 cur = buf[u];
            buf[u] = *(const uint2*)(base2 + (size_t)sP3[q0 + 4 + u] * (NC3 * 2));
            float wv = sw3[q0 + u];
            float2 f01 = __half22float2(*(__half2*)&cur.x);
            float2 f23 = __half22float2(*(__half2*)&cur.y);
            acc[0] = fmaf(wv, fmaxf(fmaf(f01.x, A[0], Bb[0]), 0.f), acc[0]);
            acc[1] = fmaf(wv, fmaxf(fmaf(f01.y, A[1], Bb[1]), 0.f), acc[1]);
            acc[2] = fmaf(wv, fmaxf(fmaf(f23.x, A[2], Bb[2]), 0.f), acc[2]);
            acc[3] = fmaf(wv, fmaxf(fmaf(f23.y, A[3], Bb[3]), 0.f), acc[3]);
        }
    }

    float bv = __ldg(b3);
    float* op = out + (size_t)bs * NPTS + o0 * 256 + r2;
#pragma unroll
    for (int i = 0; i < 4; i++)
        op[i * 256] = fmaxf(bv + acc[i], 0.f);
}

// ---------------- launch -----------------------------------------------------
extern "C" void kernel_launch(void* const* d_in, const int* in_sizes, int n_in,
                              void* d_out, int out_size)
{
    const float* input = (const float*)d_in[0];
    const int*   neigh = (const int*)  d_in[1];
    const float* W1    = (const float*)d_in[2];
    const float* b1    = (const float*)d_in[3];
    const float* W2    = (const float*)d_in[4];
    const float* b2    = (const float*)d_in[5];
    const float* gamma = (const float*)d_in[6];
    const float* beta  = (const float*)d_in[7];
    const float* W3    = (const float*)d_in[8];
    const float* b3    = (const float*)d_in[9];
    float* out = (float*)d_out;

    static int smem_set = 0;
    if (!smem_set) {
        cudaFuncSetAttribute(k2_mma, cudaFuncAttributeMaxDynamicSharedMemorySize,
                             SM_TOTAL);
        smem_set = 1;
    }

    k1_stage1<<<(BS_TOT * NPTS) / 256, 256>>>(input, W1, b1, neigh, W2);
    k2_mma<<<48 * 128, 256, SM_TOTAL>>>(b2);
    k2b_stats<<<BS_TOT, 256>>>();
    k3_stage3<<<256 * 3, 256>>>(W3, b3, gamma, beta, out);
}

// round 17
// speedup vs baseline: 1.8926x; 1.0418x over previous
#include <cuda_runtime.h>
#include <cuda_fp16.h>
#include <cstdint>
#include <cstddef>

// Problem constants (B=8, S=24, N=4096, K=9, C1=32, C2=16)
#define BS_TOT 192
#define SDIM   24
#define NPTS   4096
#define KNB    9
#define C1V    32
#define C2V    16
#define JTOT   36864   // KNB * NPTS
#define NCOL   6144    // 192*32 columns (logical)
#define NC3    3072    // 192*16 columns of yT3
#define BN_EPS 1e-5f

// k2 smem layout: As = 288 rows x 256 B (XOR-swizzled), Ws = 16 rows x 592 B
#define SM_AS_BYTES (288 * 256)     // 73728
#define SM_WS_BYTES (16 * 592)      // 9472
#define SM_TOTAL    (SM_AS_BYTES + SM_WS_BYTES)

// ---------------- device scratch (static globals: allocation-free) ----------
__device__ __align__(16) unsigned short d_P2[JTOT]; // raw gather indices
__device__ __align__(16) unsigned short d_P3[JTOT]; // remapped loc indices (k3)
__device__ __align__(16) __half g_W2h[16 * 288];    // fp16 W2 (converted once)
__device__ float g_sum[SDIM * C2V];
__device__ float g_sumsq[SDIM * C2V];
// stage-1 out, fp16, layout [bs][p][c] (c contiguous): 48 MB
__device__ __half g_hT[(size_t)BS_TOT * NPTS * C1V];
// stage-2 out, transposed fp16: g_yT3[loc][bs*16+o], loc = r*32+c (p' = c*128+r)
__device__ __half g_yT3[(size_t)NPTS * NC3];        // 24 MB

// ---------------- packed f32x2 helpers (k1 FFMA2 path) ----------------------
__device__ __forceinline__ unsigned long long pack2(float x, float y) {
    unsigned long long r;
    asm("mov.b64 %0, {%1, %2};" : "=l"(r)
        : "r"(__float_as_uint(x)), "r"(__float_as_uint(y)));
    return r;
}
__device__ __forceinline__ float2 unpack2(unsigned long long v) {
    unsigned int a, b;
    asm("mov.b64 {%0, %1}, %2;" : "=r"(a), "=r"(b) : "l"(v));
    return make_float2(__uint_as_float(a), __uint_as_float(b));
}
#define FMA2(acc, a, b) \
    asm("fma.rn.f32x2 %0, %1, %2, %0;" : "+l"(acc) : "l"(a), "l"(b))

// ---------------- async-copy + mma helpers ----------------------------------
__device__ __forceinline__ void cp16(unsigned dst, const void* src) {
    asm volatile("cp.async.cg.shared.global [%0], [%1], 16;" :: "r"(dst), "l"(src));
}
__device__ __forceinline__ void cp_commit() {
    asm volatile("cp.async.commit_group;");
}
__device__ __forceinline__ void ldsm_x4(unsigned &r0, unsigned &r1,
                                        unsigned &r2, unsigned &r3, unsigned a) {
    asm volatile("ldmatrix.sync.aligned.m8n8.x4.shared.b16 {%0,%1,%2,%3},[%4];"
                 : "=r"(r0), "=r"(r1), "=r"(r2), "=r"(r3) : "r"(a));
}
__device__ __forceinline__ void ldsm_x4t(unsigned &r0, unsigned &r1,
                                         unsigned &r2, unsigned &r3, unsigned a) {
    asm volatile("ldmatrix.sync.aligned.m8n8.x4.trans.shared.b16 {%0,%1,%2,%3},[%4];"
                 : "=r"(r0), "=r"(r1), "=r"(r2), "=r"(r3) : "r"(a));
}
__device__ __forceinline__ void mma16816(float &d0, float &d1, float &d2, float &d3,
                                         unsigned a0, unsigned a1, unsigned a2, unsigned a3,
                                         unsigned b0, unsigned b1) {
    asm volatile("mma.sync.aligned.m16n8k16.row.col.f32.f16.f16.f32 "
                 "{%0,%1,%2,%3},{%4,%5,%6,%7},{%8,%9},{%0,%1,%2,%3};"
                 : "+f"(d0), "+f"(d1), "+f"(d2), "+f"(d3)
                 : "r"(a0), "r"(a1), "r"(a2), "r"(a3), "r"(b0), "r"(b1));
}

// ---------------- K1: stage 1 conv -> fp16 hT[bs][p][c] (+ P tables, W2h) ---
__global__ void __launch_bounds__(256) k1_stage1(
    const float* __restrict__ in, const float* __restrict__ W1,
    const float* __restrict__ b1, const int* __restrict__ neigh,
    const float* __restrict__ W2)
{
    __shared__ __align__(16) unsigned long long sw[KNB * 16];
    __shared__ unsigned long long sb[16];
    int t = threadIdx.x;

    int j = blockIdx.x * 256 + t;
    if (j < JTOT) {
        int n = j & (NPTS - 1);
        int k = j >> 12;
        int idx = neigh[n * KNB + k];
        d_P2[j] = (unsigned short)idx;
        d_P3[j] = (unsigned short)(((idx & 127) << 5) + (idx >> 7));  // raw loc
    }
    if (j < 16 * 288) g_W2h[j] = __float2half(__ldg(W2 + j));
    if (j < SDIM * C2V) { g_sum[j] = 0.f; g_sumsq[j] = 0.f; }

    if (t < KNB * 16) {
        int q = t >> 4, oh = t & 15;
        sw[t] = pack2(W1[(2 * oh) * KNB + q], W1[(2 * oh + 1) * KNB + q]);
    }
    if (t < 16) sb[t] = pack2(b1[2 * t], b1[2 * t + 1]);
    __syncthreads();

    int g  = blockIdx.x * 256 + t;
    int bs = g >> 12;
    int pp = g & (NPTS - 1);
    const float* ip = in + (size_t)bs * JTOT;

    unsigned long long acc[16];
#pragma unroll
    for (int oh = 0; oh < 16; oh++) acc[oh] = sb[oh];

    int base = pp * KNB;
#pragma unroll
    for (int q = 0; q < KNB; q++) {
        int jt = base + q;
        float v = __ldg(ip + ((jt & (NPTS - 1)) * KNB) + (jt >> 12));
        unsigned long long v2 = pack2(v, v);
        const ulonglong2* w = (const ulonglong2*)(sw + q * 16);
#pragma unroll
        for (int oh2 = 0; oh2 < 8; oh2++) {
            ulonglong2 ww = w[oh2];
            FMA2(acc[2 * oh2],     v2, ww.x);
            FMA2(acc[2 * oh2 + 1], v2, ww.y);
        }
    }

    // relu + fp16: 64 B contiguous per point -> dense 2 KB span per warp
    uint4* hp = (uint4*)(g_hT + (size_t)(bs * NPTS + pp) * C1V);
#pragma unroll
    for (int qb = 0; qb < 4; qb++) {
        __half2 h2[4];
#pragma unroll
        for (int i = 0; i < 4; i++) {
            float2 f = unpack2(acc[4 * qb + i]);
            h2[i] = __floats2half2_rn(fmaxf(f.x, 0.f), fmaxf(f.y, 0.f));
        }
        hp[qb] = *(uint4*)h2;
    }
}

// ---------------- K2: tensor-core GEMM, pipelined cp.async, fp16 yT3 out ----
// Block (ct, r): D[o=16, col=128] = W2[16,288] x A[288,128]; A row q is point
// P2[r*288+q]; col = (bs_l, ch) with bs = ct*4+bs_l. Staged swizzled:
// unit u -> u ^ (q&15). Epilogue: padded smem transpose -> coalesced fp16
// stores into yT3[loc][bs*16+o].
__global__ void __launch_bounds__(256, 2) k2_mma(const float* __restrict__ b2)
{
    extern __shared__ char sm[];
    unsigned as_u = (unsigned)__cvta_generic_to_shared(sm);
    unsigned ws_u = as_u + SM_AS_BYTES;

    int blk = blockIdx.x;
    int r   = blk & 127;
    int ct  = blk >> 7;          // 0..47
    int t   = threadIdx.x;
    int lane = t & 31, w = t >> 5;

    // group 0: W2h (9216 B in 592 B-stride rows)
    for (int i = t; i < 576; i += 256) {
        int row = i / 36, col = i - row * 36;
        cp16(ws_u + row * 592 + col * 16, (const char*)g_W2h + i * 16);
    }
    cp_commit();
    // groups 1..18: A chunks of 16 q-rows each; unit o: bs_l=o>>2, ch=(o&3)*8
    const char* hbase = (const char*)g_hT + (size_t)ct * 4 * NPTS * 64;
    const unsigned short* Prow = d_P2 + r * 288;
#pragma unroll 1
    for (int k = 0; k < 18; k++) {
        int i = k * 256 + t;
        int q = i >> 4, o = i & 15;
        int row = __ldg(Prow + q);
        cp16(as_u + q * 256 + ((o ^ (q & 15)) << 4),
             hbase + (size_t)(o >> 2) * (NPTS * 64) + (size_t)row * 64 + (o & 3) * 16);
        cp_commit();
    }

    int g = lane >> 2;
    float d[2][4];
    {
        float bi0 = __ldg(b2 + g), bi1 = __ldg(b2 + g + 8);
        d[0][0] = bi0; d[0][1] = bi0; d[0][2] = bi1; d[0][3] = bi1;
        d[1][0] = bi0; d[1][1] = bi0; d[1][2] = bi1; d[1][3] = bi1;
    }

    int lr = lane & 15;
    unsigned aBase = ws_u + lr * 592 + ((lane >> 4) * 8) * 2;
    unsigned bBase = as_u + lr * 256 + (((w * 2 + (lane >> 4)) ^ lr) << 4);

    // phase 1: wait for W2 + chunks 0..8 (pending <= 9), mma ks 0..8
    asm volatile("cp.async.wait_group 9;" ::: "memory");
    __syncthreads();
#pragma unroll
    for (int ks = 0; ks < 9; ks++) {
        unsigned a0, a1, a2, a3, b0, b1, b2r, b3r;
        ldsm_x4(a0, a1, a2, a3, aBase + ks * 32);
        ldsm_x4t(b0, b1, b2r, b3r, bBase + ks * 4096);
        mma16816(d[0][0], d[0][1], d[0][2], d[0][3], a0, a1, a2, a3, b0, b1);
        mma16816(d[1][0], d[1][1], d[1][2], d[1][3], a0, a1, a2, a3, b2r, b3r);
    }
    // phase 2
    asm volatile("cp.async.wait_group 0;" ::: "memory");
    __syncthreads();
#pragma unroll
    for (int ks = 9; ks < 18; ks++) {
        unsigned a0, a1, a2, a3, b0, b1, b2r, b3r;
        ldsm_x4(a0, a1, a2, a3, aBase + ks * 32);
        ldsm_x4t(b0, b1, b2r, b3r, bBase + ks * 4096);
        mma16816(d[0][0], d[0][1], d[0][2], d[0][3], a0, a1, a2, a3, b0, b1);
        mma16816(d[1][0], d[1][1], d[1][2], d[1][3], a0, a1, a2, a3, b2r, b3r);
    }

    // epilogue: transpose via padded smem (72-half rows, conflict-free)
    __syncthreads();
    __half* sT = (__half*)sm;    // 32 rows x 72 halfs (144 B, 16B-aligned)
    {
        int colL = w * 16 + (lane & 3) * 2;
        int c   = colL & 31;
        int bsl = colL >> 5;
        int bo  = bsl * 16;
        sT[(c)     * 72 + bo + g]     = __float2half(d[0][0]);
        sT[(c + 1) * 72 + bo + g]     = __float2half(d[0][1]);
        sT[(c)     * 72 + bo + g + 8] = __float2half(d[0][2]);
        sT[(c + 1) * 72 + bo + g + 8] = __float2half(d[0][3]);
        sT[(c + 8) * 72 + bo + g]     = __float2half(d[1][0]);
        sT[(c + 9) * 72 + bo + g]     = __float2half(d[1][1]);
        sT[(c + 8) * 72 + bo + g + 8] = __float2half(d[1][2]);
        sT[(c + 9) * 72 + bo + g + 8] = __float2half(d[1][3]);
    }
    __syncthreads();
    {
        int rowc = t >> 3, seg = t & 7;   // 32 rows x 128 B
        *(uint4*)(g_yT3 + (size_t)(r * 32 + rowc) * NC3 + ct * 64 + seg * 8) =
            *(const uint4*)(sT + rowc * 72 + seg * 8);
    }
}

// ---------------- K2b: BN stats from yT3 (coalesced fp16, fp32 accum) -------
__global__ void __launch_bounds__(256) k2b_stats()
{
    __shared__ float red[8][8][4];
    int bs = blockIdx.x;
    int t  = threadIdx.x;
    int op = t & 7;        // o pair: o = 2op, 2op+1
    int grp = t >> 3;      // 32 groups over loc

    float s0 = 0.f, s1 = 0.f, q0 = 0.f, q1 = 0.f;
    const __half* base = g_yT3 + bs * 16 + op * 2;
#pragma unroll 4
    for (int loc = grp; loc < NPTS; loc += 32) {
        __half2 v = *(const __half2*)(base + (size_t)loc * NC3);
        float2 f = __half22float2(v);
        s0 += f.x; s1 += f.y; q0 += f.x * f.x; q1 += f.y * f.y;
    }
    s0 += __shfl_down_sync(0xFFFFFFFFu, s0, 16);
    s0 += __shfl_down_sync(0xFFFFFFFFu, s0, 8);
    s1 += __shfl_down_sync(0xFFFFFFFFu, s1, 16);
    s1 += __shfl_down_sync(0xFFFFFFFFu, s1, 8);
    q0 += __shfl_down_sync(0xFFFFFFFFu, q0, 16);
    q0 += __shfl_down_sync(0xFFFFFFFFu, q0, 8);
    q1 += __shfl_down_sync(0xFFFFFFFFu, q1, 16);
    q1 += __shfl_down_sync(0xFFFFFFFFu, q1, 8);
    int wp = t >> 5, l = t & 31;
    if (l < 8) { red[wp][l][0] = s0; red[wp][l][1] = s1; red[wp][l][2] = q0; red[wp][l][3] = q1; }
    __syncthreads();
    if (t < 8) {
        float S0 = 0.f, S1 = 0.f, Q0 = 0.f, Q1 = 0.f;
#pragma unroll
        for (int wq = 0; wq < 8; wq++) {
            S0 += red[wq][t][0]; S1 += red[wq][t][1];
            Q0 += red[wq][t][2]; Q1 += red[wq][t][3];
        }
        int ss = bs % SDIM;
        atomicAdd(&g_sum[ss * C2V + 2 * t],     S0);
        atomicAdd(&g_sum[ss * C2V + 2 * t + 1], S1);
        atomicAdd(&g_sumsq[ss * C2V + 2 * t],     Q0);
        atomicAdd(&g_sumsq[ss * C2V + 2 * t + 1], Q1);
    }
}

// ---------------- K3: transposed streaming stage-3 ---------------------------
__global__ void __launch_bounds__(256) k3_stage3(
    const float* __restrict__ W3, const float* __restrict__ b3,
    const float* __restrict__ gamma, const float* __restrict__ beta,
    float* __restrict__ out)
{
    __shared__ unsigned short sP3[160];
    __shared__ float sw3[144];

    int blk = blockIdx.x;
    int r2  = blk & 255;
    int ct  = blk >> 8;          // 0..2
    int t   = threadIdx.x;

    if (t < 144) { sP3[t] = d_P3[r2 * 144 + t]; sw3[t] = __ldg(W3 + t); }
    else if (t < 160) sP3[t] = 0;

    int col0 = ct * 1024 + t * 4;
    int bs   = col0 >> 4;
    int o0   = col0 & 15;        // in {0,4,8,12}
    int s    = bs % SDIM;

    const float inv_cnt = 1.0f / (8.0f * (float)NPTS);
    float A[4], Bb[4];
#pragma unroll
    for (int i = 0; i < 4; i++) {
        int o = o0 + i;
        float mean = g_sum[s * C2V + o] * inv_cnt;
        float var  = g_sumsq[s * C2V + o] * inv_cnt - mean * mean;
        A[i]  = __ldg(gamma + o) * rsqrtf(var + BN_EPS);
        Bb[i] = __ldg(beta + o) - mean * A[i];
    }
    __syncthreads();

    const char* base2 = (const char*)(g_yT3 + col0);
    float acc[4] = { 0.f, 0.f, 0.f, 0.f };

    uint2 buf[4];
#pragma unroll
    for (int i = 0; i < 4; i++)
        buf[i] = *(const uint2*)(base2 + (size_t)sP3[i] * (NC3 * 2));

#pragma unroll 2
    for (int q0 = 0; q0 < 144; q0 += 4) {
#pragma unroll
        for (int u = 0; u < 4; u++) {
            uint2 cur = buf[u];
            buf[u] = *(const uint2*)(base2 + (size_t)sP3[q0 + 4 + u] * (NC3 * 2));
            float wv = sw3[q0 + u];
            float2 f01 = __half22float2(*(__half2*)&cur.x);
            float2 f23 = __half22float2(*(__half2*)&cur.y);
            acc[0] = fmaf(wv, fmaxf(fmaf(f01.x, A[0], Bb[0]), 0.f), acc[0]);
            acc[1] = fmaf(wv, fmaxf(fmaf(f01.y, A[1], Bb[1]), 0.f), acc[1]);
            acc[2] = fmaf(wv, fmaxf(fmaf(f23.x, A[2], Bb[2]), 0.f), acc[2]);
            acc[3] = fmaf(wv, fmaxf(fmaf(f23.y, A[3], Bb[3]), 0.f), acc[3]);
        }
    }

    float bv = __ldg(b3);
    float* op = out + (size_t)bs * NPTS + o0 * 256 + r2;
#pragma unroll
    for (int i = 0; i < 4; i++)
        op[i * 256] = fmaxf(bv + acc[i], 0.f);
}

// ---------------- launch -----------------------------------------------------
extern "C" void kernel_launch(void* const* d_in, const int* in_sizes, int n_in,
                              void* d_out, int out_size)
{
    const float* input = (const float*)d_in[0];
    const int*   neigh = (const int*)  d_in[1];
    const float* W1    = (const float*)d_in[2];
    const float* b1    = (const float*)d_in[3];
    const float* W2    = (const float*)d_in[4];
    const float* b2    = (const float*)d_in[5];
    const float* gamma = (const float*)d_in[6];
    const float* beta  = (const float*)d_in[7];
    const float* W3    = (const float*)d_in[8];
    const float* b3    = (const float*)d_in[9];
    float* out = (float*)d_out;

    static int smem_set = 0;
    if (!smem_set) {
        cudaFuncSetAttribute(k2_mma, cudaFuncAttributeMaxDynamicSharedMemorySize,
                             SM_TOTAL);
        smem_set = 1;
    }

    k1_stage1<<<(BS_TOT * NPTS) / 256, 256>>>(input, W1, b1, neigh, W2);
    k2_mma<<<48 * 128, 256, SM_TOTAL>>>(b2);
    k2b_stats<<<BS_TOT, 256>>>();
    k3_stage3<<<256 * 3, 256>>>(W3, b3, gamma, beta, out);
}